// round 5
// baseline (speedup 1.0000x reference)
#include <cuda_runtime.h>
#include <math.h>
#include <stdint.h>

typedef unsigned long long u64;

#define DD   256
#define BB   8
#define CHK  64
#define NC   64
#define TLEN 4096

#define SA    260               // activation tile row stride (floats)
#define PAN   16                // k-panel width
#define NPAN  (DD/PAN)          // 16
#define SBT   18                // B^T panel stride (conflict-free LDS.64)
#define SNB   260               // normal-orientation panel stride
#define XTILE (16*SA)           // 4160 floats
#define BTBUF (2*256*SBT)       // 9216 floats (double buffer; gemmN needs 2*16*260=8320)

// ---------------- persistent state (double-buffered) ----------------
static __device__ float S_w1f[2][4][BB][DD*DD];
static __device__ float S_w2 [2][6][BB][DD*DD];
static __device__ float S_w1v[2][2][BB][DD];
static __device__ float S_wsk[2][2][BB][DD];

// ---------------- per-chunk scratch ----------------
static __device__ float SC_k [BB][CHK*DD];
static __device__ float SC_v [BB][CHK*DD];
static __device__ float SC_q [BB][CHK*DD];
static __device__ float SC_h2[6][BB][CHK*DD];
static __device__ float SC_g [4][BB][CHK*DD];
static __device__ float SC_pre[6][BB][CHK*DD];
static __device__ float SC_eta[BB][CHK];
static __device__ float SC_alpha[BB][CHK];
static __device__ float SC_vsum[BB][CHK];
static __device__ float SC_gs[2][BB][CHK];
static __device__ float SC_abar[BB];

// ---------------- helpers ----------------
__device__ __forceinline__ void fmaX2(u64 &d, u64 a, u64 b){
    asm("fma.rn.f32x2 %0, %1, %2, %0;" : "+l"(d) : "l"(a), "l"(b));
}
__device__ __forceinline__ u64 pk2(float lo, float hi){
    u64 r; asm("mov.b64 %0, {%1, %2};" : "=l"(r) : "f"(lo), "f"(hi)); return r;
}
__device__ __forceinline__ float2 up2(u64 v){
    float lo, hi; asm("mov.b64 {%0, %1}, %2;" : "=f"(lo), "=f"(hi) : "l"(v));
    return make_float2(lo, hi);
}
__device__ __forceinline__ float red2(u64 v){ float2 t = up2(v); return t.x + t.y; }

__device__ __forceinline__ void cpa8(uint32_t d, const float* s){
    asm volatile("cp.async.ca.shared.global [%0], [%1], 8;" :: "r"(d), "l"(s));
}
__device__ __forceinline__ void cpa16(uint32_t d, const float* s){
    asm volatile("cp.async.cg.shared.global [%0], [%1], 16;" :: "r"(d), "l"(s));
}
__device__ __forceinline__ void cpcommit(){ asm volatile("cp.async.commit_group;"); }
__device__ __forceinline__ void cpwait(){ asm volatile("cp.async.wait_group 0;"); }

__device__ __forceinline__ float geluf(float z){
    return 0.5f*z*(1.0f + erff(z*0.70710678118654752f));
}
__device__ __forceinline__ float dgeluf(float z){
    float cdf = 0.5f*(1.0f + erff(z*0.70710678118654752f));
    float pdf = expf(-0.5f*z*z)*0.39894228040143267f;
    return cdf + z*pdf;
}
__device__ __forceinline__ float warp_sum(float v){
    #pragma unroll
    for(int o=16;o>0;o>>=1) v += __shfl_xor_sync(0xffffffffu, v, o);
    return v;
}

// load 16x256 global -> smem tile (stride SA), 128 threads
__device__ __forceinline__ void load_tile16(float* dst, const float* __restrict__ src){
    const int tid = threadIdx.x;
    #pragma unroll
    for(int l=0;l<8;l++){
        int idx = tid + l*128;
        int r = idx>>6, qc = (idx&63)<<2;
        *reinterpret_cast<float4*>(dst + r*SA + qc) =
            *reinterpret_cast<const float4*>(src + r*DD + qc);
    }
}

// stage B^T panel p (rows j=0..255, k in [p*16,+16)) into buf p&1 via cp.async
__device__ __forceinline__ void stageTB(uint32_t btu, const float* __restrict__ Bg, int p){
    const int tid = threadIdx.x;
    uint32_t base = btu + (uint32_t)((p&1)*(256*SBT*4));
    const float* src = Bg + p*PAN;
    #pragma unroll
    for(int l=0;l<16;l++){
        int idx = tid + l*128;                 // 2048 8B-chunks
        int j = idx>>3, cc = (idx&7)*2;
        cpa8(base + (uint32_t)((j*SBT + cc)*4), src + (size_t)j*DD + cc);
    }
    cpcommit();
}

// ---------------- TB GEMM: OUT[t,col]=sum_c A[t,c]*B[col,c]  (128 thr) ----------------
__device__ __forceinline__ void gemmTB(const float* As, const float* __restrict__ Bg,
                                       float* Bt, u64 (&acc)[4][8]){
    const int tid = threadIdx.x, wid = tid>>5, tx = tid&31;
    uint32_t btu = (uint32_t)__cvta_generic_to_shared(Bt);
    #pragma unroll
    for(int r=0;r<4;r++)
        #pragma unroll
        for(int j=0;j<8;j++) acc[r][j] = 0ull;

    stageTB(btu, Bg, 0);
    #pragma unroll 1
    for(int p=0;p<NPAN;p++){
        cpwait(); __syncthreads();
        if(p+1 < NPAN) stageTB(btu, Bg, p+1);
        const float* Ar = As + wid*4*SA + p*PAN;
        const float* Bl = Bt + (p&1)*256*SBT + tx*SBT;
        #pragma unroll
        for(int c2=0;c2<8;c2++){
            u64 a0 = *reinterpret_cast<const u64*>(Ar + 0*SA + 2*c2);
            u64 a1 = *reinterpret_cast<const u64*>(Ar + 1*SA + 2*c2);
            u64 a2 = *reinterpret_cast<const u64*>(Ar + 2*SA + 2*c2);
            u64 a3 = *reinterpret_cast<const u64*>(Ar + 3*SA + 2*c2);
            #pragma unroll
            for(int j=0;j<8;j++){
                u64 b = *reinterpret_cast<const u64*>(Bl + j*32*SBT + 2*c2);
                fmaX2(acc[0][j], a0, b);
                fmaX2(acc[1][j], a1, b);
                fmaX2(acc[2][j], a2, b);
                fmaX2(acc[3][j], a3, b);
            }
        }
    }
    __syncthreads();
}

// stage normal panel p (rows c=p*16..+15, all 256 cols) into buf p&1
__device__ __forceinline__ void stageN(uint32_t btu, const float* __restrict__ Bg, int p){
    const int tid = threadIdx.x;
    uint32_t base = btu + (uint32_t)((p&1)*(16*SNB*4));
    const float* src = Bg + (size_t)p*PAN*DD;
    #pragma unroll
    for(int l=0;l<8;l++){
        int idx = tid + l*128;                 // 1024 16B-chunks
        int cc = idx>>6, qc = (idx&63)<<2;
        cpa16(base + (uint32_t)((cc*SNB + qc)*4), src + (size_t)cc*DD + qc);
    }
    cpcommit();
}

// ---------------- normal GEMM: OUT[t,j]=sum_c A[t,c]*B[c,j]  (128 thr) ----------------
// lane owns col pairs (2tx+64p, +1)
__device__ __forceinline__ void gemmN(const float* As, const float* __restrict__ Bg,
                                      float* Bt, u64 (&acc)[4][4]){
    const int tid = threadIdx.x, wid = tid>>5, tx = tid&31;
    uint32_t btu = (uint32_t)__cvta_generic_to_shared(Bt);
    #pragma unroll
    for(int r=0;r<4;r++)
        #pragma unroll
        for(int pp=0;pp<4;pp++) acc[r][pp] = 0ull;

    stageN(btu, Bg, 0);
    #pragma unroll 1
    for(int p=0;p<NPAN;p++){
        cpwait(); __syncthreads();
        if(p+1 < NPAN) stageN(btu, Bg, p+1);
        const float* Ar = As + wid*4*SA + p*PAN;
        const float* Bl = Bt + (p&1)*16*SNB + 2*tx;
        #pragma unroll
        for(int cc=0;cc<16;cc++){
            u64 a0 = pk2(Ar[0*SA+cc], Ar[0*SA+cc]);
            u64 a1 = pk2(Ar[1*SA+cc], Ar[1*SA+cc]);
            u64 a2 = pk2(Ar[2*SA+cc], Ar[2*SA+cc]);
            u64 a3 = pk2(Ar[3*SA+cc], Ar[3*SA+cc]);
            #pragma unroll
            for(int pp=0;pp<4;pp++){
                u64 b = *reinterpret_cast<const u64*>(Bl + cc*SNB + 64*pp);
                fmaX2(acc[0][pp], a0, b);
                fmaX2(acc[1][pp], a1, b);
                fmaX2(acc[2][pp], a2, b);
                fmaX2(acc[3][pp], a3, b);
            }
        }
    }
    __syncthreads();
}

// ---------------- K0: initialize per-batch state ----------------
__global__ void k0_init(const float* __restrict__ k1w, const float* __restrict__ k2w,
                        const float* __restrict__ v1w, const float* __restrict__ v2w,
                        const float* __restrict__ q1w, const float* __restrict__ q2w,
                        const float* __restrict__ e1w, const float* __restrict__ e2w,
                        const float* __restrict__ esw, const float* __restrict__ a1w,
                        const float* __restrict__ a2w, const float* __restrict__ asw,
                        const float* __restrict__ m1w, const float* __restrict__ m2w){
    const int gid = blockIdx.x*blockDim.x + threadIdx.x;
    const int m = blockIdx.y;
    if(m<4){
        const float* src = (m==0)?k1w:(m==1)?v1w:(m==2)?q1w:m1w;
        float v = src[gid];
        #pragma unroll
        for(int b=0;b<BB;b++) S_w1f[0][m][b][gid] = v;
    } else if(m<10){
        const int s = m-4;
        const float* src = (s==0)?k2w:(s==1)?v2w:(s==2)?q2w:(s==3)?e2w:(s==4)?a2w:m2w;
        float v = src[gid];
        #pragma unroll
        for(int b=0;b<BB;b++) S_w2[0][s][b][gid] = v;
    } else {
        if(gid < DD){
            #pragma unroll
            for(int b=0;b<BB;b++){
                S_w1v[0][0][b][gid] = e1w[gid];
                S_w1v[0][1][b][gid] = a1w[gid];
                S_wsk[0][0][b][gid] = esw[gid];
                S_wsk[0][1][b][gid] = asw[gid];
            }
        }
    }
}

// ---------------- K1: forwards k,v,q + (eta,alpha) (grid 128 x 128thr) ----------------
__global__ void __launch_bounds__(128) k1_forward(const float* __restrict__ x, int chunk){
    extern __shared__ float sm[];
    float* Xs = sm;
    float* Hs = sm + XTILE;
    float* Bt = sm + 2*XTILE;
    const int tid = threadIdx.x, wid = tid>>5, tx = tid&31;
    const int bx = blockIdx.x;
    const int th = bx&3, gg = (bx>>2)&3, b = bx>>4;
    const int cur = chunk&1;
    const int tok0 = chunk*CHK + th*16;

    load_tile16(Xs, x + ((size_t)b*TLEN + tok0)*DD);

    u64 acc[4][8];
    if(gg < 3){
        gemmTB(Xs, S_w2[cur][gg][b], Bt, acc);
        #pragma unroll
        for(int r=0;r<4;r++)
            #pragma unroll
            for(int j=0;j<8;j++)
                Hs[(wid*4+r)*SA + tx + 32*j] = geluf(red2(acc[r][j]));
        gemmTB(Hs, S_w1f[cur][gg][b], Bt, acc);
        #pragma unroll
        for(int r=0;r<4;r++){
            const int row = th*16 + wid*4 + r;
            float out[8]; float ss = 0.f, vs = 0.f;
            #pragma unroll
            for(int j=0;j<8;j++){
                const int col = tx + 32*j;
                float o = Xs[(wid*4+r)*SA + col] + red2(acc[r][j]);
                out[j] = o; ss += o*o; vs += o;
            }
            if(gg==1){
                vs = warp_sum(vs);
                #pragma unroll
                for(int j=0;j<8;j++) SC_v[b][row*DD + tx + 32*j] = out[j];
                if(tx==0) SC_vsum[b][row] = vs;
            } else {
                ss = warp_sum(ss);
                float inv = 1.f / fmaxf(sqrtf(ss), 1e-6f);
                float* dst = (gg==0)? SC_k[b] : SC_q[b];
                #pragma unroll
                for(int j=0;j<8;j++) dst[row*DD + tx + 32*j] = out[j]*inv;
            }
        }
    } else {
        #pragma unroll 1
        for(int si=0;si<2;si++){
            gemmTB(Xs, S_w2[cur][3+si][b], Bt, acc);
            const float* wsk = S_wsk[cur][si][b];
            const float* w1v = S_w1v[cur][si][b];
            #pragma unroll
            for(int r=0;r<4;r++){
                const int row = th*16 + wid*4 + r;
                float p = 0.f;
                #pragma unroll
                for(int j=0;j<8;j++){
                    float h = geluf(red2(acc[r][j]));
                    p += Xs[(wid*4+r)*SA + tx + 32*j]*wsk[tx+32*j] + h*w1v[tx+32*j];
                }
                p = warp_sum(p);
                if(tx==0){
                    if(si==0){ float sp = (p>20.f)? p : log1pf(expf(p)); SC_eta[b][row] = sp*0.001f; }
                    else       SC_alpha[b][row] = 1.f/(1.f+expf(-p));
                }
            }
        }
    }
}

// ---------------- K2: per-token update terms + output (grid 224 x 128thr) ----------------
__global__ void __launch_bounds__(128) k2_token(float* __restrict__ dout, int chunk){
    extern __shared__ float sm[];
    const int tid = threadIdx.x, wid = tid>>5, tx = tid&31;
    const int bx = blockIdx.x, cur = chunk&1;

    if(bx < 128){
        float* Ks = sm;
        float* Hs = sm + XTILE;
        float* Gs = sm + 2*XTILE;
        float* Bt = sm + 3*XTILE;
        const int th = bx&3, f = (bx>>2)&3, b = bx>>4;
        const int s = (f==3)? 5 : f;

        load_tile16(Ks, SC_k[b] + th*16*DD);

        u64 acc[4][8]; float zreg[4][8];
        gemmTB(Ks, S_w2[cur][s][b], Bt, acc);
        #pragma unroll
        for(int r=0;r<4;r++)
            #pragma unroll
            for(int j=0;j<8;j++){
                float z = red2(acc[r][j]); zreg[r][j] = z;
                float h = geluf(z);
                Hs[(wid*4+r)*SA + tx + 32*j] = h;
                SC_h2[s][b][(th*16 + wid*4 + r)*DD + tx + 32*j] = h;
            }
        gemmTB(Hs, S_w1f[cur][f][b], Bt, acc);
        #pragma unroll
        for(int r=0;r<4;r++)
            #pragma unroll
            for(int j=0;j<8;j++){
                const int row = th*16 + wid*4 + r, col = tx + 32*j;
                float g = 2.f*(Ks[(wid*4+r)*SA + col] + red2(acc[r][j]) - SC_v[b][row*DD+col]);
                Gs[(wid*4+r)*SA + col] = g;
                SC_g[f][b][row*DD+col] = g;
                Ks[(wid*4+r)*SA + col] = dgeluf(zreg[r][j]);   // repurpose Ks as dgelu tile
            }
        u64 accN[4][4];
        gemmN(Gs, S_w1f[cur][f][b], Bt, accN);
        #pragma unroll
        for(int r=0;r<4;r++){
            const int row = th*16 + wid*4 + r;
            #pragma unroll
            for(int pp=0;pp<4;pp++){
                float2 v = up2(accN[r][pp]);
                const int c0 = 2*tx + 64*pp;
                SC_pre[s][b][row*DD + c0]     = v.x * Ks[(wid*4+r)*SA + c0];
                SC_pre[s][b][row*DD + c0 + 1] = v.y * Ks[(wid*4+r)*SA + c0 + 1];
            }
        }
    } else if(bx < 192){
        float* Ks = sm;
        float* Bt = sm + XTILE;
        const int i = bx-128, th = i&3, si = (i>>2)&1, b = i>>3;
        const int s = 3+si;

        load_tile16(Ks, SC_k[b] + th*16*DD);

        u64 acc[4][8];
        gemmTB(Ks, S_w2[cur][s][b], Bt, acc);
        const float* wsk = S_wsk[cur][si][b];
        const float* w1v = S_w1v[cur][si][b];
        #pragma unroll
        for(int r=0;r<4;r++){
            const int row = th*16 + wid*4 + r;
            float zr[8]; float p = 0.f;
            #pragma unroll
            for(int j=0;j<8;j++){
                float z = red2(acc[r][j]); zr[j] = z;
                float h = geluf(z);
                SC_h2[s][b][row*DD + tx + 32*j] = h;
                p += Ks[(wid*4+r)*SA + tx + 32*j]*wsk[tx+32*j] + h*w1v[tx+32*j];
            }
            p = warp_sum(p);
            float g = 2.f*(256.f*p - SC_vsum[b][row]);
            if(tx==0) SC_gs[si][b][row] = g;
            #pragma unroll
            for(int j=0;j<8;j++)
                SC_pre[s][b][row*DD + tx + 32*j] = g * w1v[tx+32*j] * dgeluf(zr[j]);
        }
    } else {
        float* Qs = sm;
        float* Hs = sm + XTILE;
        float* Bt = sm + 2*XTILE;
        const int i = bx-192, th = i&3, b = i>>2;

        load_tile16(Qs, SC_q[b] + th*16*DD);

        u64 acc[4][8];
        gemmTB(Qs, S_w2[cur][5][b], Bt, acc);
        #pragma unroll
        for(int r=0;r<4;r++)
            #pragma unroll
            for(int j=0;j<8;j++)
                Hs[(wid*4+r)*SA + tx + 32*j] = geluf(red2(acc[r][j]));
        gemmTB(Hs, S_w1f[cur][3][b], Bt, acc);
        #pragma unroll
        for(int r=0;r<4;r++)
            #pragma unroll
            for(int j=0;j<8;j++){
                size_t off = ((size_t)b*TLEN + (size_t)chunk*CHK + th*16 + wid*4 + r)*DD + tx + 32*j;
                dout[off] = Qs[(wid*4+r)*SA + tx + 32*j] + red2(acc[r][j]);
            }
        if(th==0 && tid==0){
            float p = 1.f;
            #pragma unroll
            for(int t=0;t<CHK;t++) p *= SC_alpha[b][t];
            SC_abar[b] = p;
        }
    }
}

// ---------------- K3: weight updates (grid 656 x 256thr) ----------------
__global__ void __launch_bounds__(256) k3_weights(int chunk){
    extern __shared__ float sm[];
    float* Ges = sm;            // 64 x 66
    float* Bs  = sm + 64*66;    // 64 x 132
    const int tid = threadIdx.x, wid = tid>>5, tx = tid&31;
    const int bx = blockIdx.x;
    const int cur = chunk&1, nxt = cur^1;

    if(bx < 640){
        int b, ot, ch;
        const float *A, *Bsrc, *Wold; float* Wnew;
        if(bx < 512){
            b = bx>>6; int r = bx&63;
            int f = r>>4, m = (r>>3)&1; ot = (r>>1)&3; ch = r&1;
            int s = (f==3)? 5 : f;
            if(m==0){ A = SC_g[f][b];   Bsrc = SC_h2[s][b]; Wold = S_w1f[cur][f][b]; Wnew = S_w1f[nxt][f][b]; }
            else    { A = SC_pre[s][b]; Bsrc = SC_k[b];     Wold = S_w2[cur][s][b];  Wnew = S_w2[nxt][s][b]; }
        } else {
            int i = bx-512; b = i>>4; int r = i&15;
            int si = r>>3; ot = (r>>1)&3; ch = r&1;
            int s = 3+si;
            A = SC_pre[s][b]; Bsrc = SC_k[b]; Wold = S_w2[cur][s][b]; Wnew = S_w2[nxt][s][b];
        }
        const float abar = SC_abar[b];
        const float* eta = SC_eta[b];
        uint32_t bsu = (uint32_t)__cvta_generic_to_shared(Bs);

        // stage B cols [ch*128,+128) via cp.async (overlaps Ges staging + W prefetch)
        #pragma unroll
        for(int l=0;l<8;l++){
            int idx = tid + l*256;
            int t = idx>>5, qc = (idx&31)<<2;
            cpa16(bsu + (uint32_t)((t*132 + qc)*4), Bsrc + (size_t)t*DD + ch*128 + qc);
        }
        cpcommit();

        // stage Ges[t][o] = A[t, ot*64+o]*eta[t] (regular ld/st)
        #pragma unroll
        for(int l=0;l<4;l++){
            int idx = tid + l*256;
            int t = idx>>4, oq = (idx&15)<<2;
            float e = eta[t];
            float4 v = *reinterpret_cast<const float4*>(A + t*DD + ot*64 + oq);
            float2* p = reinterpret_cast<float2*>(Ges + t*66 + oq);
            p[0] = make_float2(v.x*e, v.y*e);
            p[1] = make_float2(v.z*e, v.w*e);
        }

        // prefetch Wold tile rows into registers (latency hides under K loop)
        float4 wpre[4][2];
        #pragma unroll
        for(int rp=0;rp<4;rp++){
            const size_t off0 = (size_t)(ot*64 + wid*8 + 2*rp)*DD + ch*128 + tx*4;
            wpre[rp][0] = *reinterpret_cast<const float4*>(Wold + off0);
            wpre[rp][1] = *reinterpret_cast<const float4*>(Wold + off0 + DD);
        }

        cpwait();
        __syncthreads();

        u64 acc[4][4];
        #pragma unroll
        for(int rp=0;rp<4;rp++)
            #pragma unroll
            for(int j=0;j<4;j++) acc[rp][j] = 0ull;

        #pragma unroll 4
        for(int t=0;t<64;t++){
            u64 a[4];
            #pragma unroll
            for(int rp=0;rp<4;rp++)
                a[rp] = *reinterpret_cast<const u64*>(Ges + t*66 + wid*8 + 2*rp);
            float4 bv = *reinterpret_cast<const float4*>(Bs + t*132 + tx*4);
            u64 b0 = pk2(bv.x,bv.x), b1 = pk2(bv.y,bv.y), b2 = pk2(bv.z,bv.z), b3 = pk2(bv.w,bv.w);
            #pragma unroll
            for(int rp=0;rp<4;rp++){
                fmaX2(acc[rp][0], a[rp], b0);
                fmaX2(acc[rp][1], a[rp], b1);
                fmaX2(acc[rp][2], a[rp], b2);
                fmaX2(acc[rp][3], a[rp], b3);
            }
        }
        #pragma unroll
        for(int rp=0;rp<4;rp++){
            const size_t off0 = (size_t)(ot*64 + wid*8 + 2*rp)*DD + ch*128 + tx*4;
            float2 c0 = up2(acc[rp][0]), c1 = up2(acc[rp][1]);
            float2 c2 = up2(acc[rp][2]), c3 = up2(acc[rp][3]);
            float4 w0 = wpre[rp][0], w1 = wpre[rp][1];
            float4 o0 = make_float4(abar*w0.x - c0.x, abar*w0.y - c1.x,
                                    abar*w0.z - c2.x, abar*w0.w - c3.x);
            float4 o1 = make_float4(abar*w1.x - c0.y, abar*w1.y - c1.y,
                                    abar*w1.z - c2.y, abar*w1.w - c3.y);
            *reinterpret_cast<float4*>(Wnew + off0)      = o0;
            *reinterpret_cast<float4*>(Wnew + off0 + DD) = o1;
        }
    } else {
        const int i = bx-640, b = i>>1, si = i&1, s = 3+si;
        const float abar = SC_abar[b];
        const int j = tid;
        float aA = 0.f, aB = 0.f;
        #pragma unroll 4
        for(int t=0;t<CHK;t++){
            float ge = SC_gs[si][b][t]*SC_eta[b][t];
            aA += ge * SC_h2[s][b][t*DD + j];
            aB += ge * SC_k[b][t*DD + j];
        }
        S_w1v[nxt][si][b][j] = abar*S_w1v[cur][si][b][j] - aA;
        S_wsk[nxt][si][b][j] = abar*S_wsk[cur][si][b][j] - aB;
    }
}

// ---------------- launch ----------------
#define SMEM1 ((2*XTILE + BTBUF)*4)      // 70144 B
#define SMEM2 ((3*XTILE + BTBUF)*4)      // 86784 B
#define SMEM3 ((64*66 + 64*132)*4)       // 50688 B

extern "C" void kernel_launch(void* const* d_in, const int* in_sizes, int n_in,
                              void* d_out, int out_size){
    (void)in_sizes; (void)n_in; (void)out_size;
    const float* x   = (const float*)d_in[0];
    const float* k1w = (const float*)d_in[1];
    const float* k2w = (const float*)d_in[2];
    const float* v1w = (const float*)d_in[3];
    const float* v2w = (const float*)d_in[4];
    const float* q1w = (const float*)d_in[5];
    const float* q2w = (const float*)d_in[6];
    const float* e1w = (const float*)d_in[7];
    const float* e2w = (const float*)d_in[8];
    const float* esw = (const float*)d_in[9];
    const float* a1w = (const float*)d_in[10];
    const float* a2w = (const float*)d_in[11];
    const float* asw = (const float*)d_in[12];
    const float* m1w = (const float*)d_in[13];
    const float* m2w = (const float*)d_in[14];
    float* out = (float*)d_out;

    cudaFuncSetAttribute(k1_forward, cudaFuncAttributeMaxDynamicSharedMemorySize, SMEM1);
    cudaFuncSetAttribute(k2_token,   cudaFuncAttributeMaxDynamicSharedMemorySize, SMEM2);
    cudaFuncSetAttribute(k3_weights, cudaFuncAttributeMaxDynamicSharedMemorySize, SMEM3);

    k0_init<<<dim3(DD*DD/256, 11), 256>>>(k1w,k2w,v1w,v2w,q1w,q2w,e1w,e2w,esw,a1w,a2w,asw,m1w,m2w);

    for(int c=0;c<NC;c++){
        k1_forward<<<128, 128, SMEM1>>>(x, c);
        k2_token  <<<224, 128, SMEM2>>>(out, c);
        k3_weights<<<656, 256, SMEM3>>>(c);
    }
}

// round 6
// speedup vs baseline: 1.0617x; 1.0617x over previous
#include <cuda_runtime.h>
#include <math.h>

typedef unsigned long long u64;

#define DD   256
#define BB   8
#define CHK  64
#define NC   64
#define TLEN 4096

#define SA    260               // activation tile row stride (floats)
#define STB   34                // B^T staging stride
#define SNB   260               // normal-orientation staging stride
#define XTILE (16*SA)           // 4160 floats
#define BTBUF (256*STB)         // 8704 floats (gemmN needs 32*260=8320, fits)

// ---------------- persistent state (double-buffered) ----------------
// states: 0=k 1=v 2=q 3=eta 4=alpha 5=mem ; full-w1 index f: k,v,q,mem -> 0,1,2,3
static __device__ float S_w1f[2][4][BB][DD*DD];
static __device__ float S_w2 [2][6][BB][DD*DD];
static __device__ float S_w1v[2][2][BB][DD];
static __device__ float S_wsk[2][2][BB][DD];

// ---------------- per-chunk scratch ----------------
static __device__ float SC_k [BB][CHK*DD];
static __device__ float SC_v [BB][CHK*DD];
static __device__ float SC_q [BB][CHK*DD];
static __device__ float SC_h2[6][BB][CHK*DD];
static __device__ float SC_g [4][BB][CHK*DD];
static __device__ float SC_pre[6][BB][CHK*DD];
static __device__ float SC_eta[BB][CHK];
static __device__ float SC_alpha[BB][CHK];
static __device__ float SC_vsum[BB][CHK];
static __device__ float SC_gs[2][BB][CHK];
static __device__ float SC_abar[BB];

// ---------------- helpers ----------------
__device__ __forceinline__ void fmaX2(u64 &d, u64 a, u64 b){
    asm("fma.rn.f32x2 %0, %1, %2, %0;" : "+l"(d) : "l"(a), "l"(b));
}
__device__ __forceinline__ u64 pk2(float lo, float hi){
    u64 r; asm("mov.b64 %0, {%1, %2};" : "=l"(r) : "f"(lo), "f"(hi)); return r;
}
__device__ __forceinline__ float2 up2(u64 v){
    float lo, hi; asm("mov.b64 {%0, %1}, %2;" : "=f"(lo), "=f"(hi) : "l"(v));
    return make_float2(lo, hi);
}
__device__ __forceinline__ float red2(u64 v){ float2 t = up2(v); return t.x + t.y; }

__device__ __forceinline__ float geluf(float z){
    return 0.5f*z*(1.0f + erff(z*0.70710678118654752f));
}
__device__ __forceinline__ float dgeluf(float z){
    float cdf = 0.5f*(1.0f + erff(z*0.70710678118654752f));
    float pdf = expf(-0.5f*z*z)*0.39894228040143267f;
    return cdf + z*pdf;
}
__device__ __forceinline__ float warp_sum(float v){
    #pragma unroll
    for(int o=16;o>0;o>>=1) v += __shfl_xor_sync(0xffffffffu, v, o);
    return v;
}

// load 16x256 global -> smem tile (stride SA), 256 threads
__device__ __forceinline__ void load_tile16(float* dst, const float* __restrict__ src){
    const int tid = threadIdx.x;
    #pragma unroll
    for(int l=0;l<4;l++){
        int idx = tid + l*256;            // 1024 float4s
        int r = idx>>6, qc = (idx&63)<<2;
        *reinterpret_cast<float4*>(dst + r*SA + qc) =
            *reinterpret_cast<const float4*>(src + r*DD + qc);
    }
}

// ---------------- TB GEMM (256 thr): OUT[t,col]=sum_c A[t,c]*B[col,c] ----------------
// warps: rw=(wid&3) -> rows rw*4..+3 ; jh=wid>>2 -> cols jh*128 + tx + 32*jj (jj<4)
__device__ __forceinline__ void gemmTB(const float* As, const float* __restrict__ Bg,
                                       float* Bt, u64 (&acc)[4][4]){
    const int tid = threadIdx.x, tx = tid&31;
    const int rw = (tid>>5)&3, jh = tid>>7;
    #pragma unroll
    for(int r=0;r<4;r++)
        #pragma unroll
        for(int j=0;j<4;j++) acc[r][j] = 0ull;

    for(int c0=0;c0<DD;c0+=32){
        // stage B[j][c0..c0+31] -> Bt[j*STB + cc]   (2048 float4, 8/thread)
        #pragma unroll
        for(int l=0;l<8;l++){
            int idx = tid + l*256;
            int j = idx>>3, qc = (idx&7)<<2;
            float4 v = *reinterpret_cast<const float4*>(Bg + (size_t)j*DD + c0 + qc);
            float2* p = reinterpret_cast<float2*>(Bt + j*STB + qc);
            p[0] = make_float2(v.x, v.y);
            p[1] = make_float2(v.z, v.w);
        }
        __syncthreads();
        const float* Ar = As + rw*4*SA + c0;
        const float* Bl = Bt + (jh*128 + tx)*STB;
        #pragma unroll
        for(int c2=0;c2<16;c2++){
            u64 a0 = *reinterpret_cast<const u64*>(Ar + 0*SA + 2*c2);
            u64 a1 = *reinterpret_cast<const u64*>(Ar + 1*SA + 2*c2);
            u64 a2 = *reinterpret_cast<const u64*>(Ar + 2*SA + 2*c2);
            u64 a3 = *reinterpret_cast<const u64*>(Ar + 3*SA + 2*c2);
            #pragma unroll
            for(int jj=0;jj<4;jj++){
                u64 b = *reinterpret_cast<const u64*>(Bl + jj*32*STB + 2*c2);
                fmaX2(acc[0][jj], a0, b);
                fmaX2(acc[1][jj], a1, b);
                fmaX2(acc[2][jj], a2, b);
                fmaX2(acc[3][jj], a3, b);
            }
        }
        __syncthreads();
    }
}

// ---------------- normal GEMM (256 thr): OUT[t,j]=sum_c A[t,c]*B[c,j] ----------------
// cols: jh*128 + 2*tx + 64*pp (+1), pp<2
__device__ __forceinline__ void gemmN(const float* As, const float* __restrict__ Bg,
                                      float* Bt, u64 (&acc)[4][2]){
    const int tid = threadIdx.x, tx = tid&31;
    const int rw = (tid>>5)&3, jh = tid>>7;
    #pragma unroll
    for(int r=0;r<4;r++)
        #pragma unroll
        for(int pp=0;pp<2;pp++) acc[r][pp] = 0ull;

    for(int c0=0;c0<DD;c0+=32){
        #pragma unroll
        for(int l=0;l<8;l++){
            int idx = tid + l*256;
            int cc = idx>>6, qc = (idx&63)<<2;
            *reinterpret_cast<float4*>(Bt + cc*SNB + qc) =
                *reinterpret_cast<const float4*>(Bg + (size_t)(c0+cc)*DD + qc);
        }
        __syncthreads();
        const float* Ar = As + rw*4*SA + c0;
        const float* Bl = Bt + jh*128 + 2*tx;
        #pragma unroll
        for(int cc=0;cc<32;cc++){
            u64 a0 = pk2(Ar[0*SA+cc], Ar[0*SA+cc]);
            u64 a1 = pk2(Ar[1*SA+cc], Ar[1*SA+cc]);
            u64 a2 = pk2(Ar[2*SA+cc], Ar[2*SA+cc]);
            u64 a3 = pk2(Ar[3*SA+cc], Ar[3*SA+cc]);
            #pragma unroll
            for(int pp=0;pp<2;pp++){
                u64 b = *reinterpret_cast<const u64*>(Bl + cc*SNB + 64*pp);
                fmaX2(acc[0][pp], a0, b);
                fmaX2(acc[1][pp], a1, b);
                fmaX2(acc[2][pp], a2, b);
                fmaX2(acc[3][pp], a3, b);
            }
        }
        __syncthreads();
    }
}

// ---------------- K0: initialize per-batch state ----------------
__global__ void k0_init(const float* __restrict__ k1w, const float* __restrict__ k2w,
                        const float* __restrict__ v1w, const float* __restrict__ v2w,
                        const float* __restrict__ q1w, const float* __restrict__ q2w,
                        const float* __restrict__ e1w, const float* __restrict__ e2w,
                        const float* __restrict__ esw, const float* __restrict__ a1w,
                        const float* __restrict__ a2w, const float* __restrict__ asw,
                        const float* __restrict__ m1w, const float* __restrict__ m2w){
    const int gid = blockIdx.x*blockDim.x + threadIdx.x;
    const int m = blockIdx.y;
    if(m<4){
        const float* src = (m==0)?k1w:(m==1)?v1w:(m==2)?q1w:m1w;
        float v = src[gid];
        #pragma unroll
        for(int b=0;b<BB;b++) S_w1f[0][m][b][gid] = v;
    } else if(m<10){
        const int s = m-4;
        const float* src = (s==0)?k2w:(s==1)?v2w:(s==2)?q2w:(s==3)?e2w:(s==4)?a2w:m2w;
        float v = src[gid];
        #pragma unroll
        for(int b=0;b<BB;b++) S_w2[0][s][b][gid] = v;
    } else {
        if(gid < DD){
            #pragma unroll
            for(int b=0;b<BB;b++){
                S_w1v[0][0][b][gid] = e1w[gid];
                S_w1v[0][1][b][gid] = a1w[gid];
                S_wsk[0][0][b][gid] = esw[gid];
                S_wsk[0][1][b][gid] = asw[gid];
            }
        }
    }
}

// ---------------- K1: forwards k,v,q + (eta,alpha) (grid 128 x 256thr) ----------------
__global__ void __launch_bounds__(256) k1_forward(const float* __restrict__ x, int chunk){
    extern __shared__ float sm[];
    float* Xs  = sm;
    float* Hs  = sm + XTILE;
    float* Bt  = sm + 2*XTILE;
    float* Red = sm + 2*XTILE + BTBUF;      // 32 floats
    const int tid = threadIdx.x, tx = tid&31;
    const int rw = (tid>>5)&3, jh = tid>>7;
    const int bx = blockIdx.x;
    const int th = bx&3, gg = (bx>>2)&3, b = bx>>4;
    const int cur = chunk&1;
    const int tok0 = chunk*CHK + th*16;

    load_tile16(Xs, x + ((size_t)b*TLEN + tok0)*DD);

    u64 acc[4][4];
    if(gg < 3){
        gemmTB(Xs, S_w2[cur][gg][b], Bt, acc);
        #pragma unroll
        for(int r=0;r<4;r++)
            #pragma unroll
            for(int jj=0;jj<4;jj++)
                Hs[(rw*4+r)*SA + jh*128 + tx + 32*jj] = geluf(red2(acc[r][jj]));
        gemmTB(Hs, S_w1f[cur][gg][b], Bt, acc);

        float out[4][4];
        #pragma unroll
        for(int r=0;r<4;r++){
            const int r2 = rw*4+r;
            float s = 0.f;
            #pragma unroll
            for(int jj=0;jj<4;jj++){
                const int col = jh*128 + tx + 32*jj;
                float o = Xs[r2*SA + col] + red2(acc[r][jj]);
                out[r][jj] = o;
                s += (gg==1)? o : o*o;
            }
            s = warp_sum(s);
            if(tx==0) Red[r2*2 + jh] = s;
        }
        __syncthreads();
        if(gg==1){
            #pragma unroll
            for(int r=0;r<4;r++){
                const int r2 = rw*4+r, row = th*16 + r2;
                #pragma unroll
                for(int jj=0;jj<4;jj++)
                    SC_v[b][row*DD + jh*128 + tx + 32*jj] = out[r][jj];
                if(jh==0 && tx==0) SC_vsum[b][row] = Red[r2*2] + Red[r2*2+1];
            }
        } else {
            float* dst = (gg==0)? SC_k[b] : SC_q[b];
            #pragma unroll
            for(int r=0;r<4;r++){
                const int r2 = rw*4+r, row = th*16 + r2;
                float inv = 1.f / fmaxf(sqrtf(Red[r2*2] + Red[r2*2+1]), 1e-6f);
                #pragma unroll
                for(int jj=0;jj<4;jj++)
                    dst[row*DD + jh*128 + tx + 32*jj] = out[r][jj]*inv;
            }
        }
    } else {
        #pragma unroll 1
        for(int si=0;si<2;si++){
            gemmTB(Xs, S_w2[cur][3+si][b], Bt, acc);
            const float* wsk = S_wsk[cur][si][b];
            const float* w1v = S_w1v[cur][si][b];
            #pragma unroll
            for(int r=0;r<4;r++){
                const int r2 = rw*4+r;
                float p = 0.f;
                #pragma unroll
                for(int jj=0;jj<4;jj++){
                    const int col = jh*128 + tx + 32*jj;
                    float h = geluf(red2(acc[r][jj]));
                    p += Xs[r2*SA + col]*wsk[col] + h*w1v[col];
                }
                p = warp_sum(p);
                if(tx==0) Red[r2*2 + jh] = p;
            }
            __syncthreads();
            if(jh==0 && tx==0){
                #pragma unroll
                for(int r=0;r<4;r++){
                    const int r2 = rw*4+r, row = th*16 + r2;
                    float pt = Red[r2*2] + Red[r2*2+1];
                    if(si==0){ float sp = (pt>20.f)? pt : log1pf(expf(pt)); SC_eta[b][row] = sp*0.001f; }
                    else       SC_alpha[b][row] = 1.f/(1.f+expf(-pt));
                }
            }
            __syncthreads();
        }
    }
}

// ---------------- K2: per-token update terms + output (grid 224 x 256thr) ----------------
__global__ void __launch_bounds__(256) k2_token(float* __restrict__ dout, int chunk){
    extern __shared__ float sm[];
    const int tid = threadIdx.x, tx = tid&31;
    const int rw = (tid>>5)&3, jh = tid>>7;
    const int bx = blockIdx.x, cur = chunk&1;
    u64 acc[4][4];

    if(bx < 128){
        float* Ks = sm;
        float* Hs = sm + XTILE;
        float* Gs = sm + 2*XTILE;
        float* Bt = sm + 3*XTILE;
        const int th = bx&3, f = (bx>>2)&3, b = bx>>4;
        const int s = (f==3)? 5 : f;

        load_tile16(Ks, SC_k[b] + th*16*DD);

        float zreg[4][4];
        gemmTB(Ks, S_w2[cur][s][b], Bt, acc);
        #pragma unroll
        for(int r=0;r<4;r++)
            #pragma unroll
            for(int jj=0;jj<4;jj++){
                const int r2 = rw*4+r, col = jh*128 + tx + 32*jj;
                float z = red2(acc[r][jj]); zreg[r][jj] = z;
                float h = geluf(z);
                Hs[r2*SA + col] = h;
                SC_h2[s][b][(th*16 + r2)*DD + col] = h;
            }
        gemmTB(Hs, S_w1f[cur][f][b], Bt, acc);
        #pragma unroll
        for(int r=0;r<4;r++)
            #pragma unroll
            for(int jj=0;jj<4;jj++){
                const int r2 = rw*4+r, col = jh*128 + tx + 32*jj;
                const int row = th*16 + r2;
                float g = 2.f*(Ks[r2*SA + col] + red2(acc[r][jj]) - SC_v[b][row*DD + col]);
                Gs[r2*SA + col] = g;
                SC_g[f][b][row*DD + col] = g;
                Ks[r2*SA + col] = dgeluf(zreg[r][jj]);   // repurpose Ks as dgelu tile
            }
        u64 accN[4][2];
        gemmN(Gs, S_w1f[cur][f][b], Bt, accN);
        #pragma unroll
        for(int r=0;r<4;r++){
            const int r2 = rw*4+r, row = th*16 + r2;
            #pragma unroll
            for(int pp=0;pp<2;pp++){
                float2 v = up2(accN[r][pp]);
                const int c0 = jh*128 + 2*tx + 64*pp;
                SC_pre[s][b][row*DD + c0]     = v.x * Ks[r2*SA + c0];
                SC_pre[s][b][row*DD + c0 + 1] = v.y * Ks[r2*SA + c0 + 1];
            }
        }
    } else if(bx < 192){
        float* Ks  = sm;
        float* Bt  = sm + XTILE;
        float* Red = sm + XTILE + BTBUF;
        const int i = bx-128, th = i&3, si = (i>>2)&1, b = i>>3;
        const int s = 3+si;

        load_tile16(Ks, SC_k[b] + th*16*DD);

        gemmTB(Ks, S_w2[cur][s][b], Bt, acc);
        const float* wsk = S_wsk[cur][si][b];
        const float* w1v = S_w1v[cur][si][b];
        float zr[4][4];
        #pragma unroll
        for(int r=0;r<4;r++){
            const int r2 = rw*4+r;
            float p = 0.f;
            #pragma unroll
            for(int jj=0;jj<4;jj++){
                const int col = jh*128 + tx + 32*jj;
                float z = red2(acc[r][jj]); zr[r][jj] = z;
                float h = geluf(z);
                SC_h2[s][b][(th*16 + r2)*DD + col] = h;
                p += Ks[r2*SA + col]*wsk[col] + h*w1v[col];
            }
            p = warp_sum(p);
            if(tx==0) Red[r2*2 + jh] = p;
        }
        __syncthreads();
        #pragma unroll
        for(int r=0;r<4;r++){
            const int r2 = rw*4+r, row = th*16 + r2;
            float pt = Red[r2*2] + Red[r2*2+1];
            float g = 2.f*(256.f*pt - SC_vsum[b][row]);
            if(jh==0 && tx==0) SC_gs[si][b][row] = g;
            #pragma unroll
            for(int jj=0;jj<4;jj++){
                const int col = jh*128 + tx + 32*jj;
                SC_pre[s][b][row*DD + col] = g * w1v[col] * dgeluf(zr[r][jj]);
            }
        }
    } else {
        float* Qs = sm;
        float* Hs = sm + XTILE;
        float* Bt = sm + 2*XTILE;
        const int i = bx-192, th = i&3, b = i>>2;

        load_tile16(Qs, SC_q[b] + th*16*DD);

        gemmTB(Qs, S_w2[cur][5][b], Bt, acc);
        #pragma unroll
        for(int r=0;r<4;r++)
            #pragma unroll
            for(int jj=0;jj<4;jj++)
                Hs[(rw*4+r)*SA + jh*128 + tx + 32*jj] = geluf(red2(acc[r][jj]));
        gemmTB(Hs, S_w1f[cur][3][b], Bt, acc);
        #pragma unroll
        for(int r=0;r<4;r++)
            #pragma unroll
            for(int jj=0;jj<4;jj++){
                const int r2 = rw*4+r, col = jh*128 + tx + 32*jj;
                size_t off = ((size_t)b*TLEN + (size_t)chunk*CHK + th*16 + r2)*DD + col;
                dout[off] = Qs[r2*SA + col] + red2(acc[r][jj]);
            }
        if(th==0 && tid==0){
            float p = 1.f;
            #pragma unroll
            for(int t=0;t<CHK;t++) p *= SC_alpha[b][t];
            SC_abar[b] = p;
        }
    }
}

// ---------------- K3: weight updates (grid 656 x 256thr)  [R2-proven version] ----------
__global__ void __launch_bounds__(256) k3_weights(int chunk){
    extern __shared__ float sm[];
    float* Ges = sm;            // 64 x 66
    float* Bs  = sm + 64*66;    // 64 x 132
    const int tid = threadIdx.x, wid = tid>>5, tx = tid&31;
    const int bx = blockIdx.x;
    const int cur = chunk&1, nxt = cur^1;

    if(bx < 640){
        int b, ot, ch;
        const float *A, *Bsrc, *Wold; float* Wnew;
        if(bx < 512){
            b = bx>>6; int r = bx&63;
            int f = r>>4, m = (r>>3)&1; ot = (r>>1)&3; ch = r&1;
            int s = (f==3)? 5 : f;
            if(m==0){ A = SC_g[f][b];   Bsrc = SC_h2[s][b]; Wold = S_w1f[cur][f][b]; Wnew = S_w1f[nxt][f][b]; }
            else    { A = SC_pre[s][b]; Bsrc = SC_k[b];     Wold = S_w2[cur][s][b];  Wnew = S_w2[nxt][s][b]; }
        } else {
            int i = bx-512; b = i>>4; int r = i&15;
            int si = r>>3; ot = (r>>1)&3; ch = r&1;
            int s = 3+si;
            A = SC_pre[s][b]; Bsrc = SC_k[b]; Wold = S_w2[cur][s][b]; Wnew = S_w2[nxt][s][b];
        }
        const float abar = SC_abar[b];
        const float* eta = SC_eta[b];

        #pragma unroll
        for(int l=0;l<8;l++){
            int idx = tid + l*256;
            int t = idx>>5, qc = (idx&31)<<2;
            *reinterpret_cast<float4*>(Bs + t*132 + qc) =
                *reinterpret_cast<const float4*>(Bsrc + t*DD + ch*128 + qc);
        }
        #pragma unroll
        for(int l=0;l<4;l++){
            int idx = tid + l*256;
            int t = idx>>4, oq = (idx&15)<<2;
            float e = eta[t];
            float4 v = *reinterpret_cast<const float4*>(A + t*DD + ot*64 + oq);
            float2* p = reinterpret_cast<float2*>(Ges + t*66 + oq);
            p[0] = make_float2(v.x*e, v.y*e);
            p[1] = make_float2(v.z*e, v.w*e);
        }
        __syncthreads();

        u64 acc[4][4];
        #pragma unroll
        for(int rp=0;rp<4;rp++)
            #pragma unroll
            for(int j=0;j<4;j++) acc[rp][j] = 0ull;

        #pragma unroll 4
        for(int t=0;t<64;t++){
            u64 a[4];
            #pragma unroll
            for(int rp=0;rp<4;rp++)
                a[rp] = *reinterpret_cast<const u64*>(Ges + t*66 + wid*8 + 2*rp);
            float4 bv = *reinterpret_cast<const float4*>(Bs + t*132 + tx*4);
            u64 b0 = pk2(bv.x,bv.x), b1 = pk2(bv.y,bv.y), b2 = pk2(bv.z,bv.z), b3 = pk2(bv.w,bv.w);
            #pragma unroll
            for(int rp=0;rp<4;rp++){
                fmaX2(acc[rp][0], a[rp], b0);
                fmaX2(acc[rp][1], a[rp], b1);
                fmaX2(acc[rp][2], a[rp], b2);
                fmaX2(acc[rp][3], a[rp], b3);
            }
        }
        #pragma unroll
        for(int rp=0;rp<4;rp++){
            const int row0 = ot*64 + wid*8 + 2*rp;
            size_t off0 = (size_t)row0*DD + ch*128 + tx*4;
            float4 w0 = *reinterpret_cast<const float4*>(Wold + off0);
            float4 w1 = *reinterpret_cast<const float4*>(Wold + off0 + DD);
            float2 c0 = up2(acc[rp][0]), c1 = up2(acc[rp][1]);
            float2 c2 = up2(acc[rp][2]), c3 = up2(acc[rp][3]);
            float4 o0 = make_float4(abar*w0.x - c0.x, abar*w0.y - c1.x,
                                    abar*w0.z - c2.x, abar*w0.w - c3.x);
            float4 o1 = make_float4(abar*w1.x - c0.y, abar*w1.y - c1.y,
                                    abar*w1.z - c2.y, abar*w1.w - c3.y);
            *reinterpret_cast<float4*>(Wnew + off0)      = o0;
            *reinterpret_cast<float4*>(Wnew + off0 + DD) = o1;
        }
    } else {
        const int i = bx-640, b = i>>1, si = i&1, s = 3+si;
        const float abar = SC_abar[b];
        const int j = tid;
        float aA = 0.f, aB = 0.f;
        #pragma unroll 4
        for(int t=0;t<CHK;t++){
            float ge = SC_gs[si][b][t]*SC_eta[b][t];
            aA += ge * SC_h2[s][b][t*DD + j];
            aB += ge * SC_k[b][t*DD + j];
        }
        S_w1v[nxt][si][b][j] = abar*S_w1v[cur][si][b][j] - aA;
        S_wsk[nxt][si][b][j] = abar*S_wsk[cur][si][b][j] - aB;
    }
}

// ---------------- launch ----------------
#define SMEM1 ((2*XTILE + BTBUF + 32)*4)      // 68864 B
#define SMEM2 ((3*XTILE + BTBUF + 32)*4)      // 85504 B
#define SMEM3 ((64*66 + 64*132)*4)            // 50688 B

extern "C" void kernel_launch(void* const* d_in, const int* in_sizes, int n_in,
                              void* d_out, int out_size){
    (void)in_sizes; (void)n_in; (void)out_size;
    const float* x   = (const float*)d_in[0];
    const float* k1w = (const float*)d_in[1];
    const float* k2w = (const float*)d_in[2];
    const float* v1w = (const float*)d_in[3];
    const float* v2w = (const float*)d_in[4];
    const float* q1w = (const float*)d_in[5];
    const float* q2w = (const float*)d_in[6];
    const float* e1w = (const float*)d_in[7];
    const float* e2w = (const float*)d_in[8];
    const float* esw = (const float*)d_in[9];
    const float* a1w = (const float*)d_in[10];
    const float* a2w = (const float*)d_in[11];
    const float* asw = (const float*)d_in[12];
    const float* m1w = (const float*)d_in[13];
    const float* m2w = (const float*)d_in[14];
    float* out = (float*)d_out;

    cudaFuncSetAttribute(k1_forward, cudaFuncAttributeMaxDynamicSharedMemorySize, SMEM1);
    cudaFuncSetAttribute(k2_token,   cudaFuncAttributeMaxDynamicSharedMemorySize, SMEM2);
    cudaFuncSetAttribute(k3_weights, cudaFuncAttributeMaxDynamicSharedMemorySize, SMEM3);

    k0_init<<<dim3(DD*DD/256, 11), 256>>>(k1w,k2w,v1w,v2w,q1w,q2w,e1w,e2w,esw,a1w,a2w,asw,m1w,m2w);

    for(int c=0;c<NC;c++){
        k1_forward<<<128, 256, SMEM1>>>(x, c);
        k2_token  <<<224, 256, SMEM2>>>(out, c);
        k3_weights<<<656, 256, SMEM3>>>(c);
    }
}

// round 7
// speedup vs baseline: 1.0701x; 1.0079x over previous
#include <cuda_runtime.h>
#include <math.h>

typedef unsigned long long u64;

#define DD   256
#define BB   8
#define CHK  64
#define NC   64
#define TLEN 4096

#define SA    260               // activation tile row stride (floats)
#define STB   34                // B^T staging stride (conflict-free LDS.64)
#define SNB   260               // normal-orientation staging stride
#define XTILE (16*SA)           // 4160 floats
#define BT2   17408             // double buffer: max(2*256*34, 2*32*260) floats

// ---------------- persistent state (double-buffered) ----------------
// states: 0=k 1=v 2=q 3=eta 4=alpha 5=mem ; full-w1 index f: k,v,q,mem -> 0,1,2,3
static __device__ float S_w1f[2][4][BB][DD*DD];
static __device__ float S_w2 [2][6][BB][DD*DD];
static __device__ float S_w1v[2][2][BB][DD];
static __device__ float S_wsk[2][2][BB][DD];

// ---------------- per-chunk scratch ----------------
static __device__ float SC_k [BB][CHK*DD];
static __device__ float SC_v [BB][CHK*DD];
static __device__ float SC_q [BB][CHK*DD];
static __device__ float SC_h2[6][BB][CHK*DD];
static __device__ float SC_g [4][BB][CHK*DD];
static __device__ float SC_pre[6][BB][CHK*DD];
static __device__ float SC_eta[BB][CHK];
static __device__ float SC_alpha[BB][CHK];
static __device__ float SC_vsum[BB][CHK];
static __device__ float SC_gs[2][BB][CHK];
static __device__ float SC_abar[BB];

// ---------------- helpers ----------------
__device__ __forceinline__ void fmaX2(u64 &d, u64 a, u64 b){
    asm("fma.rn.f32x2 %0, %1, %2, %0;" : "+l"(d) : "l"(a), "l"(b));
}
__device__ __forceinline__ u64 pk2(float lo, float hi){
    u64 r; asm("mov.b64 %0, {%1, %2};" : "=l"(r) : "f"(lo), "f"(hi)); return r;
}
__device__ __forceinline__ float2 up2(u64 v){
    float lo, hi; asm("mov.b64 {%0, %1}, %2;" : "=f"(lo), "=f"(hi) : "l"(v));
    return make_float2(lo, hi);
}
__device__ __forceinline__ float red2(u64 v){ float2 t = up2(v); return t.x + t.y; }

__device__ __forceinline__ float geluf(float z){
    return 0.5f*z*(1.0f + erff(z*0.70710678118654752f));
}
__device__ __forceinline__ float dgeluf(float z){
    float cdf = 0.5f*(1.0f + erff(z*0.70710678118654752f));
    float pdf = expf(-0.5f*z*z)*0.39894228040143267f;
    return cdf + z*pdf;
}
__device__ __forceinline__ float warp_sum(float v){
    #pragma unroll
    for(int o=16;o>0;o>>=1) v += __shfl_xor_sync(0xffffffffu, v, o);
    return v;
}

// load 16x256 global -> smem tile (stride SA), 256 threads
__device__ __forceinline__ void load_tile16(float* dst, const float* __restrict__ src){
    const int tid = threadIdx.x;
    #pragma unroll
    for(int l=0;l<4;l++){
        int idx = tid + l*256;            // 1024 float4s
        int r = idx>>6, qc = (idx&63)<<2;
        *reinterpret_cast<float4*>(dst + r*SA + qc) =
            *reinterpret_cast<const float4*>(src + r*DD + qc);
    }
}

// ---------------- TB GEMM (256 thr, reg-staged double-buffered panels) --------------
// OUT[t,col] = sum_c A[t,c]*B[col,c]; warps: rw=(wid&3) rows rw*4..+3 ;
// jh=wid>>2 cols jh*128 + tx + 32*jj (jj<4). Panels of 32 k.
__device__ __forceinline__ void gemmTB(const float* As, const float* __restrict__ Bg,
                                       float* Bt, u64 (&acc)[4][4]){
    const int tid = threadIdx.x, tx = tid&31;
    const int rw = (tid>>5)&3, jh = tid>>7;
    const int j0 = tid>>3, qc = (tid&7)<<2;     // staged rows j0+32l, cols qc..qc+3
    #pragma unroll
    for(int r=0;r<4;r++)
        #pragma unroll
        for(int j=0;j<4;j++) acc[r][j] = 0ull;

    float4 rb[8];
    // preload + store panel 0 into buf 0
    #pragma unroll
    for(int l=0;l<8;l++)
        rb[l] = *reinterpret_cast<const float4*>(Bg + (size_t)(j0+32*l)*DD + qc);
    #pragma unroll
    for(int l=0;l<8;l++){
        float2* p = reinterpret_cast<float2*>(Bt + (j0+32*l)*STB + qc);
        p[0] = make_float2(rb[l].x, rb[l].y);
        p[1] = make_float2(rb[l].z, rb[l].w);
    }
    __syncthreads();

    #pragma unroll 2
    for(int p=0;p<8;p++){
        if(p<7){
            const float* src = Bg + (p+1)*32 + qc;
            #pragma unroll
            for(int l=0;l<8;l++)
                rb[l] = *reinterpret_cast<const float4*>(src + (size_t)(j0+32*l)*DD);
        }
        const float* Ar = As + rw*4*SA + p*32;
        const float* Bl = Bt + (p&1)*256*STB + (jh*128 + tx)*STB;
        #pragma unroll
        for(int c2=0;c2<16;c2++){
            u64 a0 = *reinterpret_cast<const u64*>(Ar + 0*SA + 2*c2);
            u64 a1 = *reinterpret_cast<const u64*>(Ar + 1*SA + 2*c2);
            u64 a2 = *reinterpret_cast<const u64*>(Ar + 2*SA + 2*c2);
            u64 a3 = *reinterpret_cast<const u64*>(Ar + 3*SA + 2*c2);
            #pragma unroll
            for(int jj=0;jj<4;jj++){
                u64 b = *reinterpret_cast<const u64*>(Bl + jj*32*STB + 2*c2);
                fmaX2(acc[0][jj], a0, b);
                fmaX2(acc[1][jj], a1, b);
                fmaX2(acc[2][jj], a2, b);
                fmaX2(acc[3][jj], a3, b);
            }
        }
        if(p<7){
            float* dstb = Bt + ((p+1)&1)*256*STB;
            #pragma unroll
            for(int l=0;l<8;l++){
                float2* q = reinterpret_cast<float2*>(dstb + (j0+32*l)*STB + qc);
                q[0] = make_float2(rb[l].x, rb[l].y);
                q[1] = make_float2(rb[l].z, rb[l].w);
            }
            __syncthreads();
        }
    }
}

// ---------------- normal GEMM (256 thr, reg-staged double-buffered panels) ----------
// OUT[t,j]=sum_c A[t,c]*B[c,j]; cols jh*128 + 2*tx + 64*pp (+1), pp<2.
__device__ __forceinline__ void gemmN(const float* As, const float* __restrict__ Bg,
                                      float* Bt, u64 (&acc)[4][2]){
    const int tid = threadIdx.x, tx = tid&31;
    const int rw = (tid>>5)&3, jh = tid>>7;
    const int cc0 = tid>>6, qn = (tid&63)<<2;   // staged rows cc0+4l, cols qn..qn+3
    #pragma unroll
    for(int r=0;r<4;r++)
        #pragma unroll
        for(int pp=0;pp<2;pp++) acc[r][pp] = 0ull;

    float4 rb[8];
    #pragma unroll
    for(int l=0;l<8;l++)
        rb[l] = *reinterpret_cast<const float4*>(Bg + (size_t)(cc0+4*l)*DD + qn);
    #pragma unroll
    for(int l=0;l<8;l++)
        *reinterpret_cast<float4*>(Bt + (cc0+4*l)*SNB + qn) = rb[l];
    __syncthreads();

    #pragma unroll 2
    for(int p=0;p<8;p++){
        if(p<7){
            const float* src = Bg + (size_t)((p+1)*32 + cc0)*DD + qn;
            #pragma unroll
            for(int l=0;l<8;l++)
                rb[l] = *reinterpret_cast<const float4*>(src + (size_t)(4*l)*DD);
        }
        const float* Ar = As + rw*4*SA + p*32;
        const float* Bl = Bt + (p&1)*32*SNB + jh*128 + 2*tx;
        #pragma unroll
        for(int cc=0;cc<32;cc++){
            u64 a0 = pk2(Ar[0*SA+cc], Ar[0*SA+cc]);
            u64 a1 = pk2(Ar[1*SA+cc], Ar[1*SA+cc]);
            u64 a2 = pk2(Ar[2*SA+cc], Ar[2*SA+cc]);
            u64 a3 = pk2(Ar[3*SA+cc], Ar[3*SA+cc]);
            #pragma unroll
            for(int pp=0;pp<2;pp++){
                u64 b = *reinterpret_cast<const u64*>(Bl + cc*SNB + 64*pp);
                fmaX2(acc[0][pp], a0, b);
                fmaX2(acc[1][pp], a1, b);
                fmaX2(acc[2][pp], a2, b);
                fmaX2(acc[3][pp], a3, b);
            }
        }
        if(p<7){
            float* dstb = Bt + ((p+1)&1)*32*SNB;
            #pragma unroll
            for(int l=0;l<8;l++)
                *reinterpret_cast<float4*>(dstb + (cc0+4*l)*SNB + qn) = rb[l];
            __syncthreads();
        }
    }
}

// ---------------- K0: initialize per-batch state ----------------
__global__ void k0_init(const float* __restrict__ k1w, const float* __restrict__ k2w,
                        const float* __restrict__ v1w, const float* __restrict__ v2w,
                        const float* __restrict__ q1w, const float* __restrict__ q2w,
                        const float* __restrict__ e1w, const float* __restrict__ e2w,
                        const float* __restrict__ esw, const float* __restrict__ a1w,
                        const float* __restrict__ a2w, const float* __restrict__ asw,
                        const float* __restrict__ m1w, const float* __restrict__ m2w){
    const int gid = blockIdx.x*blockDim.x + threadIdx.x;
    const int m = blockIdx.y;
    if(m<4){
        const float* src = (m==0)?k1w:(m==1)?v1w:(m==2)?q1w:m1w;
        float v = src[gid];
        #pragma unroll
        for(int b=0;b<BB;b++) S_w1f[0][m][b][gid] = v;
    } else if(m<10){
        const int s = m-4;
        const float* src = (s==0)?k2w:(s==1)?v2w:(s==2)?q2w:(s==3)?e2w:(s==4)?a2w:m2w;
        float v = src[gid];
        #pragma unroll
        for(int b=0;b<BB;b++) S_w2[0][s][b][gid] = v;
    } else {
        if(gid < DD){
            #pragma unroll
            for(int b=0;b<BB;b++){
                S_w1v[0][0][b][gid] = e1w[gid];
                S_w1v[0][1][b][gid] = a1w[gid];
                S_wsk[0][0][b][gid] = esw[gid];
                S_wsk[0][1][b][gid] = asw[gid];
            }
        }
    }
}

// ---------------- K1: forwards k,v,q + (eta,alpha) (grid 128 x 256thr) ----------------
__global__ void __launch_bounds__(256) k1_forward(const float* __restrict__ x, int chunk){
    extern __shared__ float sm[];
    float* Xs  = sm;
    float* Hs  = sm + XTILE;
    float* Bt  = sm + 2*XTILE;
    float* Red = sm + 2*XTILE + BT2;      // 32 floats
    const int tid = threadIdx.x, tx = tid&31;
    const int rw = (tid>>5)&3, jh = tid>>7;
    const int bx = blockIdx.x;
    const int th = bx&3, gg = (bx>>2)&3, b = bx>>4;
    const int cur = chunk&1;
    const int tok0 = chunk*CHK + th*16;

    load_tile16(Xs, x + ((size_t)b*TLEN + tok0)*DD);

    u64 acc[4][4];
    if(gg < 3){
        gemmTB(Xs, S_w2[cur][gg][b], Bt, acc);
        __syncthreads();
        #pragma unroll
        for(int r=0;r<4;r++)
            #pragma unroll
            for(int jj=0;jj<4;jj++)
                Hs[(rw*4+r)*SA + jh*128 + tx + 32*jj] = geluf(red2(acc[r][jj]));
        gemmTB(Hs, S_w1f[cur][gg][b], Bt, acc);

        float out[4][4];
        #pragma unroll
        for(int r=0;r<4;r++){
            const int r2 = rw*4+r;
            float s = 0.f;
            #pragma unroll
            for(int jj=0;jj<4;jj++){
                const int col = jh*128 + tx + 32*jj;
                float o = Xs[r2*SA + col] + red2(acc[r][jj]);
                out[r][jj] = o;
                s += (gg==1)? o : o*o;
            }
            s = warp_sum(s);
            if(tx==0) Red[r2*2 + jh] = s;
        }
        __syncthreads();
        if(gg==1){
            #pragma unroll
            for(int r=0;r<4;r++){
                const int r2 = rw*4+r, row = th*16 + r2;
                #pragma unroll
                for(int jj=0;jj<4;jj++)
                    SC_v[b][row*DD + jh*128 + tx + 32*jj] = out[r][jj];
                if(jh==0 && tx==0) SC_vsum[b][row] = Red[r2*2] + Red[r2*2+1];
            }
        } else {
            float* dst = (gg==0)? SC_k[b] : SC_q[b];
            #pragma unroll
            for(int r=0;r<4;r++){
                const int r2 = rw*4+r, row = th*16 + r2;
                float inv = 1.f / fmaxf(sqrtf(Red[r2*2] + Red[r2*2+1]), 1e-6f);
                #pragma unroll
                for(int jj=0;jj<4;jj++)
                    dst[row*DD + jh*128 + tx + 32*jj] = out[r][jj]*inv;
            }
        }
    } else {
        #pragma unroll 1
        for(int si=0;si<2;si++){
            gemmTB(Xs, S_w2[cur][3+si][b], Bt, acc);
            const float* wsk = S_wsk[cur][si][b];
            const float* w1v = S_w1v[cur][si][b];
            #pragma unroll
            for(int r=0;r<4;r++){
                const int r2 = rw*4+r;
                float p = 0.f;
                #pragma unroll
                for(int jj=0;jj<4;jj++){
                    const int col = jh*128 + tx + 32*jj;
                    float h = geluf(red2(acc[r][jj]));
                    p += Xs[r2*SA + col]*wsk[col] + h*w1v[col];
                }
                p = warp_sum(p);
                if(tx==0) Red[r2*2 + jh] = p;
            }
            __syncthreads();
            if(jh==0 && tx==0){
                #pragma unroll
                for(int r=0;r<4;r++){
                    const int r2 = rw*4+r, row = th*16 + r2;
                    float pt = Red[r2*2] + Red[r2*2+1];
                    if(si==0){ float sp = (pt>20.f)? pt : log1pf(expf(pt)); SC_eta[b][row] = sp*0.001f; }
                    else       SC_alpha[b][row] = 1.f/(1.f+expf(-pt));
                }
            }
            __syncthreads();
        }
    }
}

// ---------------- K2: per-token update terms + output (grid 224 x 256thr) ----------------
__global__ void __launch_bounds__(256) k2_token(float* __restrict__ dout, int chunk){
    extern __shared__ float sm[];
    const int tid = threadIdx.x, tx = tid&31;
    const int rw = (tid>>5)&3, jh = tid>>7;
    const int bx = blockIdx.x, cur = chunk&1;
    u64 acc[4][4];

    if(bx < 128){
        float* Ks = sm;
        float* Hs = sm + XTILE;
        float* Gs = sm + 2*XTILE;
        float* Bt = sm + 3*XTILE;
        const int th = bx&3, f = (bx>>2)&3, b = bx>>4;
        const int s = (f==3)? 5 : f;

        load_tile16(Ks, SC_k[b] + th*16*DD);

        float zreg[4][4];
        gemmTB(Ks, S_w2[cur][s][b], Bt, acc);
        __syncthreads();
        #pragma unroll
        for(int r=0;r<4;r++)
            #pragma unroll
            for(int jj=0;jj<4;jj++){
                const int r2 = rw*4+r, col = jh*128 + tx + 32*jj;
                float z = red2(acc[r][jj]); zreg[r][jj] = z;
                float h = geluf(z);
                Hs[r2*SA + col] = h;
                SC_h2[s][b][(th*16 + r2)*DD + col] = h;
            }
        gemmTB(Hs, S_w1f[cur][f][b], Bt, acc);
        __syncthreads();
        #pragma unroll
        for(int r=0;r<4;r++)
            #pragma unroll
            for(int jj=0;jj<4;jj++){
                const int r2 = rw*4+r, col = jh*128 + tx + 32*jj;
                const int row = th*16 + r2;
                float g = 2.f*(Ks[r2*SA + col] + red2(acc[r][jj]) - SC_v[b][row*DD + col]);
                Gs[r2*SA + col] = g;
                SC_g[f][b][row*DD + col] = g;
                Ks[r2*SA + col] = dgeluf(zreg[r][jj]);   // repurpose Ks as dgelu tile
            }
        u64 accN[4][2];
        gemmN(Gs, S_w1f[cur][f][b], Bt, accN);
        #pragma unroll
        for(int r=0;r<4;r++){
            const int r2 = rw*4+r, row = th*16 + r2;
            #pragma unroll
            for(int pp=0;pp<2;pp++){
                float2 v = up2(accN[r][pp]);
                const int c0 = jh*128 + 2*tx + 64*pp;
                SC_pre[s][b][row*DD + c0]     = v.x * Ks[r2*SA + c0];
                SC_pre[s][b][row*DD + c0 + 1] = v.y * Ks[r2*SA + c0 + 1];
            }
        }
    } else if(bx < 192){
        float* Ks  = sm;
        float* Bt  = sm + XTILE;
        float* Red = sm + XTILE + BT2;
        const int i = bx-128, th = i&3, si = (i>>2)&1, b = i>>3;
        const int s = 3+si;

        load_tile16(Ks, SC_k[b] + th*16*DD);

        gemmTB(Ks, S_w2[cur][s][b], Bt, acc);
        const float* wsk = S_wsk[cur][si][b];
        const float* w1v = S_w1v[cur][si][b];
        float zr[4][4];
        #pragma unroll
        for(int r=0;r<4;r++){
            const int r2 = rw*4+r;
            float p = 0.f;
            #pragma unroll
            for(int jj=0;jj<4;jj++){
                const int col = jh*128 + tx + 32*jj;
                float z = red2(acc[r][jj]); zr[r][jj] = z;
                float h = geluf(z);
                SC_h2[s][b][(th*16 + r2)*DD + col] = h;
                p += Ks[r2*SA + col]*wsk[col] + h*w1v[col];
            }
            p = warp_sum(p);
            if(tx==0) Red[r2*2 + jh] = p;
        }
        __syncthreads();
        #pragma unroll
        for(int r=0;r<4;r++){
            const int r2 = rw*4+r, row = th*16 + r2;
            float pt = Red[r2*2] + Red[r2*2+1];
            float g = 2.f*(256.f*pt - SC_vsum[b][row]);
            if(jh==0 && tx==0) SC_gs[si][b][row] = g;
            #pragma unroll
            for(int jj=0;jj<4;jj++){
                const int col = jh*128 + tx + 32*jj;
                SC_pre[s][b][row*DD + col] = g * w1v[col] * dgeluf(zr[r][jj]);
            }
        }
    } else {
        float* Qs = sm;
        float* Hs = sm + XTILE;
        float* Bt = sm + 2*XTILE;
        const int i = bx-192, th = i&3, b = i>>2;

        load_tile16(Qs, SC_q[b] + th*16*DD);

        gemmTB(Qs, S_w2[cur][5][b], Bt, acc);
        __syncthreads();
        #pragma unroll
        for(int r=0;r<4;r++)
            #pragma unroll
            for(int jj=0;jj<4;jj++)
                Hs[(rw*4+r)*SA + jh*128 + tx + 32*jj] = geluf(red2(acc[r][jj]));
        gemmTB(Hs, S_w1f[cur][3][b], Bt, acc);
        #pragma unroll
        for(int r=0;r<4;r++)
            #pragma unroll
            for(int jj=0;jj<4;jj++){
                const int r2 = rw*4+r, col = jh*128 + tx + 32*jj;
                size_t off = ((size_t)b*TLEN + (size_t)chunk*CHK + th*16 + r2)*DD + col;
                dout[off] = Qs[r2*SA + col] + red2(acc[r][jj]);
            }
        if(th==0 && tid==0){
            float p = 1.f;
            #pragma unroll
            for(int t=0;t<CHK;t++) p *= SC_alpha[b][t];
            SC_abar[b] = p;
        }
    }
}

// ---------------- K3: weight updates (grid 656 x 256thr)  [R2-proven version] ----------
__global__ void __launch_bounds__(256) k3_weights(int chunk){
    extern __shared__ float sm[];
    float* Ges = sm;            // 64 x 66
    float* Bs  = sm + 64*66;    // 64 x 132
    const int tid = threadIdx.x, wid = tid>>5, tx = tid&31;
    const int bx = blockIdx.x;
    const int cur = chunk&1, nxt = cur^1;

    if(bx < 640){
        int b, ot, ch;
        const float *A, *Bsrc, *Wold; float* Wnew;
        if(bx < 512){
            b = bx>>6; int r = bx&63;
            int f = r>>4, m = (r>>3)&1; ot = (r>>1)&3; ch = r&1;
            int s = (f==3)? 5 : f;
            if(m==0){ A = SC_g[f][b];   Bsrc = SC_h2[s][b]; Wold = S_w1f[cur][f][b]; Wnew = S_w1f[nxt][f][b]; }
            else    { A = SC_pre[s][b]; Bsrc = SC_k[b];     Wold = S_w2[cur][s][b];  Wnew = S_w2[nxt][s][b]; }
        } else {
            int i = bx-512; b = i>>4; int r = i&15;
            int si = r>>3; ot = (r>>1)&3; ch = r&1;
            int s = 3+si;
            A = SC_pre[s][b]; Bsrc = SC_k[b]; Wold = S_w2[cur][s][b]; Wnew = S_w2[nxt][s][b];
        }
        const float abar = SC_abar[b];
        const float* eta = SC_eta[b];

        #pragma unroll
        for(int l=0;l<8;l++){
            int idx = tid + l*256;
            int t = idx>>5, qc = (idx&31)<<2;
            *reinterpret_cast<float4*>(Bs + t*132 + qc) =
                *reinterpret_cast<const float4*>(Bsrc + t*DD + ch*128 + qc);
        }
        #pragma unroll
        for(int l=0;l<4;l++){
            int idx = tid + l*256;
            int t = idx>>4, oq = (idx&15)<<2;
            float e = eta[t];
            float4 v = *reinterpret_cast<const float4*>(A + t*DD + ot*64 + oq);
            float2* p = reinterpret_cast<float2*>(Ges + t*66 + oq);
            p[0] = make_float2(v.x*e, v.y*e);
            p[1] = make_float2(v.z*e, v.w*e);
        }
        __syncthreads();

        u64 acc[4][4];
        #pragma unroll
        for(int rp=0;rp<4;rp++)
            #pragma unroll
            for(int j=0;j<4;j++) acc[rp][j] = 0ull;

        #pragma unroll 4
        for(int t=0;t<64;t++){
            u64 a[4];
            #pragma unroll
            for(int rp=0;rp<4;rp++)
                a[rp] = *reinterpret_cast<const u64*>(Ges + t*66 + wid*8 + 2*rp);
            float4 bv = *reinterpret_cast<const float4*>(Bs + t*132 + tx*4);
            u64 b0 = pk2(bv.x,bv.x), b1 = pk2(bv.y,bv.y), b2 = pk2(bv.z,bv.z), b3 = pk2(bv.w,bv.w);
            #pragma unroll
            for(int rp=0;rp<4;rp++){
                fmaX2(acc[rp][0], a[rp], b0);
                fmaX2(acc[rp][1], a[rp], b1);
                fmaX2(acc[rp][2], a[rp], b2);
                fmaX2(acc[rp][3], a[rp], b3);
            }
        }
        #pragma unroll
        for(int rp=0;rp<4;rp++){
            const int row0 = ot*64 + wid*8 + 2*rp;
            size_t off0 = (size_t)row0*DD + ch*128 + tx*4;
            float4 w0 = *reinterpret_cast<const float4*>(Wold + off0);
            float4 w1 = *reinterpret_cast<const float4*>(Wold + off0 + DD);
            float2 c0 = up2(acc[rp][0]), c1 = up2(acc[rp][1]);
            float2 c2 = up2(acc[rp][2]), c3 = up2(acc[rp][3]);
            float4 o0 = make_float4(abar*w0.x - c0.x, abar*w0.y - c1.x,
                                    abar*w0.z - c2.x, abar*w0.w - c3.x);
            float4 o1 = make_float4(abar*w1.x - c0.y, abar*w1.y - c1.y,
                                    abar*w1.z - c2.y, abar*w1.w - c3.y);
            *reinterpret_cast<float4*>(Wnew + off0)      = o0;
            *reinterpret_cast<float4*>(Wnew + off0 + DD) = o1;
        }
    } else {
        const int i = bx-640, b = i>>1, si = i&1, s = 3+si;
        const float abar = SC_abar[b];
        const int j = tid;
        float aA = 0.f, aB = 0.f;
        #pragma unroll 4
        for(int t=0;t<CHK;t++){
            float ge = SC_gs[si][b][t]*SC_eta[b][t];
            aA += ge * SC_h2[s][b][t*DD + j];
            aB += ge * SC_k[b][t*DD + j];
        }
        S_w1v[nxt][si][b][j] = abar*S_w1v[cur][si][b][j] - aA;
        S_wsk[nxt][si][b][j] = abar*S_wsk[cur][si][b][j] - aB;
    }
}

// ---------------- launch ----------------
#define SMEM1 ((2*XTILE + BT2 + 32)*4)       // 103168 B
#define SMEM2 ((3*XTILE + BT2 + 32)*4)       // 119808 B
#define SMEM3 ((64*66 + 64*132)*4)           //  50688 B

extern "C" void kernel_launch(void* const* d_in, const int* in_sizes, int n_in,
                              void* d_out, int out_size){
    (void)in_sizes; (void)n_in; (void)out_size;
    const float* x   = (const float*)d_in[0];
    const float* k1w = (const float*)d_in[1];
    const float* k2w = (const float*)d_in[2];
    const float* v1w = (const float*)d_in[3];
    const float* v2w = (const float*)d_in[4];
    const float* q1w = (const float*)d_in[5];
    const float* q2w = (const float*)d_in[6];
    const float* e1w = (const float*)d_in[7];
    const float* e2w = (const float*)d_in[8];
    const float* esw = (const float*)d_in[9];
    const float* a1w = (const float*)d_in[10];
    const float* a2w = (const float*)d_in[11];
    const float* asw = (const float*)d_in[12];
    const float* m1w = (const float*)d_in[13];
    const float* m2w = (const float*)d_in[14];
    float* out = (float*)d_out;

    cudaFuncSetAttribute(k1_forward, cudaFuncAttributeMaxDynamicSharedMemorySize, SMEM1);
    cudaFuncSetAttribute(k2_token,   cudaFuncAttributeMaxDynamicSharedMemorySize, SMEM2);
    cudaFuncSetAttribute(k3_weights, cudaFuncAttributeMaxDynamicSharedMemorySize, SMEM3);

    k0_init<<<dim3(DD*DD/256, 11), 256>>>(k1w,k2w,v1w,v2w,q1w,q2w,e1w,e2w,esw,a1w,a2w,asw,m1w,m2w);

    for(int c=0;c<NC;c++){
        k1_forward<<<128, 256, SMEM1>>>(x, c);
        k2_token  <<<224, 256, SMEM2>>>(out, c);
        k3_weights<<<656, 256, SMEM3>>>(c);
    }
}

// round 8
// speedup vs baseline: 1.0856x; 1.0145x over previous
#include <cuda_runtime.h>
#include <math.h>

typedef unsigned long long u64;

#define DD   256
#define BB   8
#define CHK  64
#define NC   64
#define TLEN 4096

#define SA    260               // activation tile row stride (floats)
#define STB   34                // B^T staging stride (conflict-free LDS.64)
#define SNB   260               // normal-orientation staging stride
#define XTILE (16*SA)           // 4160 floats
#define BT2   17408             // double buffer: max(2*256*34, 2*32*260) floats

// ---------------- persistent state (IN-PLACE updated, single buffer) ----------------
// states: 0=k 1=v 2=q 3=eta 4=alpha 5=mem ; full-w1 index f: k,v,q,mem -> 0,1,2,3
static __device__ float S_w1f[4][BB][DD*DD];
static __device__ float S_w2 [6][BB][DD*DD];
static __device__ float S_w1v[2][BB][DD];
static __device__ float S_wsk[2][BB][DD];

// ---------------- per-chunk scratch ----------------
static __device__ float SC_k [BB][CHK*DD];
static __device__ float SC_v [BB][CHK*DD];
static __device__ float SC_q [BB][CHK*DD];
static __device__ float SC_h2[6][BB][CHK*DD];
static __device__ float SC_g [4][BB][CHK*DD];
static __device__ float SC_pre[6][BB][CHK*DD];
static __device__ float SC_eta[BB][CHK];
static __device__ float SC_alpha[BB][CHK];
static __device__ float SC_vsum[BB][CHK];
static __device__ float SC_gs[2][BB][CHK];
static __device__ float SC_abar[BB];

// ---------------- helpers ----------------
__device__ __forceinline__ void fmaX2(u64 &d, u64 a, u64 b){
    asm("fma.rn.f32x2 %0, %1, %2, %0;" : "+l"(d) : "l"(a), "l"(b));
}
__device__ __forceinline__ u64 pk2(float lo, float hi){
    u64 r; asm("mov.b64 %0, {%1, %2};" : "=l"(r) : "f"(lo), "f"(hi)); return r;
}
__device__ __forceinline__ float2 up2(u64 v){
    float lo, hi; asm("mov.b64 {%0, %1}, %2;" : "=f"(lo), "=f"(hi) : "l"(v));
    return make_float2(lo, hi);
}
__device__ __forceinline__ float red2(u64 v){ float2 t = up2(v); return t.x + t.y; }

__device__ __forceinline__ float geluf(float z){
    return 0.5f*z*(1.0f + erff(z*0.70710678118654752f));
}
__device__ __forceinline__ float dgeluf(float z){
    float cdf = 0.5f*(1.0f + erff(z*0.70710678118654752f));
    float pdf = expf(-0.5f*z*z)*0.39894228040143267f;
    return cdf + z*pdf;
}
__device__ __forceinline__ float warp_sum(float v){
    #pragma unroll
    for(int o=16;o>0;o>>=1) v += __shfl_xor_sync(0xffffffffu, v, o);
    return v;
}

// load 16x256 global -> smem tile (stride SA), 256 threads
__device__ __forceinline__ void load_tile16(float* dst, const float* __restrict__ src){
    const int tid = threadIdx.x;
    #pragma unroll
    for(int l=0;l<4;l++){
        int idx = tid + l*256;            // 1024 float4s
        int r = idx>>6, qc = (idx&63)<<2;
        *reinterpret_cast<float4*>(dst + r*SA + qc) =
            *reinterpret_cast<const float4*>(src + r*DD + qc);
    }
}

// ---------------- TB GEMM (256 thr, reg-staged double-buffered panels) --------------
// OUT[t,col] = sum_c A[t,c]*B[col,c]; warps: rw=(wid&3) rows rw*4..+3 ;
// jh=wid>>2 cols jh*128 + tx + 32*jj (jj<4). Panels of 32 k.
__device__ __forceinline__ void gemmTB(const float* As, const float* __restrict__ Bg,
                                       float* Bt, u64 (&acc)[4][4]){
    const int tid = threadIdx.x, tx = tid&31;
    const int rw = (tid>>5)&3, jh = tid>>7;
    const int j0 = tid>>3, qc = (tid&7)<<2;     // staged rows j0+32l, cols qc..qc+3
    #pragma unroll
    for(int r=0;r<4;r++)
        #pragma unroll
        for(int j=0;j<4;j++) acc[r][j] = 0ull;

    float4 rb[8];
    #pragma unroll
    for(int l=0;l<8;l++)
        rb[l] = *reinterpret_cast<const float4*>(Bg + (size_t)(j0+32*l)*DD + qc);
    #pragma unroll
    for(int l=0;l<8;l++){
        float2* p = reinterpret_cast<float2*>(Bt + (j0+32*l)*STB + qc);
        p[0] = make_float2(rb[l].x, rb[l].y);
        p[1] = make_float2(rb[l].z, rb[l].w);
    }
    __syncthreads();

    #pragma unroll 2
    for(int p=0;p<8;p++){
        if(p<7){
            const float* src = Bg + (p+1)*32 + qc;
            #pragma unroll
            for(int l=0;l<8;l++)
                rb[l] = *reinterpret_cast<const float4*>(src + (size_t)(j0+32*l)*DD);
        }
        const float* Ar = As + rw*4*SA + p*32;
        const float* Bl = Bt + (p&1)*256*STB + (jh*128 + tx)*STB;
        #pragma unroll
        for(int c2=0;c2<16;c2++){
            u64 a0 = *reinterpret_cast<const u64*>(Ar + 0*SA + 2*c2);
            u64 a1 = *reinterpret_cast<const u64*>(Ar + 1*SA + 2*c2);
            u64 a2 = *reinterpret_cast<const u64*>(Ar + 2*SA + 2*c2);
            u64 a3 = *reinterpret_cast<const u64*>(Ar + 3*SA + 2*c2);
            #pragma unroll
            for(int jj=0;jj<4;jj++){
                u64 b = *reinterpret_cast<const u64*>(Bl + jj*32*STB + 2*c2);
                fmaX2(acc[0][jj], a0, b);
                fmaX2(acc[1][jj], a1, b);
                fmaX2(acc[2][jj], a2, b);
                fmaX2(acc[3][jj], a3, b);
            }
        }
        if(p<7){
            float* dstb = Bt + ((p+1)&1)*256*STB;
            #pragma unroll
            for(int l=0;l<8;l++){
                float2* q = reinterpret_cast<float2*>(dstb + (j0+32*l)*STB + qc);
                q[0] = make_float2(rb[l].x, rb[l].y);
                q[1] = make_float2(rb[l].z, rb[l].w);
            }
            __syncthreads();
        }
    }
}

// ---------------- normal GEMM (256 thr, reg-staged double-buffered panels) ----------
// OUT[t,j]=sum_c A[t,c]*B[c,j]; cols jh*128 + 2*tx + 64*pp (+1), pp<2.
__device__ __forceinline__ void gemmN(const float* As, const float* __restrict__ Bg,
                                      float* Bt, u64 (&acc)[4][2]){
    const int tid = threadIdx.x, tx = tid&31;
    const int rw = (tid>>5)&3, jh = tid>>7;
    const int cc0 = tid>>6, qn = (tid&63)<<2;   // staged rows cc0+4l, cols qn..qn+3
    #pragma unroll
    for(int r=0;r<4;r++)
        #pragma unroll
        for(int pp=0;pp<2;pp++) acc[r][pp] = 0ull;

    float4 rb[8];
    #pragma unroll
    for(int l=0;l<8;l++)
        rb[l] = *reinterpret_cast<const float4*>(Bg + (size_t)(cc0+4*l)*DD + qn);
    #pragma unroll
    for(int l=0;l<8;l++)
        *reinterpret_cast<float4*>(Bt + (cc0+4*l)*SNB + qn) = rb[l];
    __syncthreads();

    #pragma unroll 2
    for(int p=0;p<8;p++){
        if(p<7){
            const float* src = Bg + (size_t)((p+1)*32 + cc0)*DD + qn;
            #pragma unroll
            for(int l=0;l<8;l++)
                rb[l] = *reinterpret_cast<const float4*>(src + (size_t)(4*l)*DD);
        }
        const float* Ar = As + rw*4*SA + p*32;
        const float* Bl = Bt + (p&1)*32*SNB + jh*128 + 2*tx;
        #pragma unroll
        for(int cc=0;cc<32;cc++){
            u64 a0 = pk2(Ar[0*SA+cc], Ar[0*SA+cc]);
            u64 a1 = pk2(Ar[1*SA+cc], Ar[1*SA+cc]);
            u64 a2 = pk2(Ar[2*SA+cc], Ar[2*SA+cc]);
            u64 a3 = pk2(Ar[3*SA+cc], Ar[3*SA+cc]);
            #pragma unroll
            for(int pp=0;pp<2;pp++){
                u64 b = *reinterpret_cast<const u64*>(Bl + cc*SNB + 64*pp);
                fmaX2(acc[0][pp], a0, b);
                fmaX2(acc[1][pp], a1, b);
                fmaX2(acc[2][pp], a2, b);
                fmaX2(acc[3][pp], a3, b);
            }
        }
        if(p<7){
            float* dstb = Bt + ((p+1)&1)*32*SNB;
            #pragma unroll
            for(int l=0;l<8;l++)
                *reinterpret_cast<float4*>(dstb + (cc0+4*l)*SNB + qn) = rb[l];
            __syncthreads();
        }
    }
}

// ---------------- K0: initialize per-batch state ----------------
__global__ void k0_init(const float* __restrict__ k1w, const float* __restrict__ k2w,
                        const float* __restrict__ v1w, const float* __restrict__ v2w,
                        const float* __restrict__ q1w, const float* __restrict__ q2w,
                        const float* __restrict__ e1w, const float* __restrict__ e2w,
                        const float* __restrict__ esw, const float* __restrict__ a1w,
                        const float* __restrict__ a2w, const float* __restrict__ asw,
                        const float* __restrict__ m1w, const float* __restrict__ m2w){
    const int gid = blockIdx.x*blockDim.x + threadIdx.x;
    const int m = blockIdx.y;
    if(m<4){
        const float* src = (m==0)?k1w:(m==1)?v1w:(m==2)?q1w:m1w;
        float v = src[gid];
        #pragma unroll
        for(int b=0;b<BB;b++) S_w1f[m][b][gid] = v;
    } else if(m<10){
        const int s = m-4;
        const float* src = (s==0)?k2w:(s==1)?v2w:(s==2)?q2w:(s==3)?e2w:(s==4)?a2w:m2w;
        float v = src[gid];
        #pragma unroll
        for(int b=0;b<BB;b++) S_w2[s][b][gid] = v;
    } else {
        if(gid < DD){
            #pragma unroll
            for(int b=0;b<BB;b++){
                S_w1v[0][b][gid] = e1w[gid];
                S_w1v[1][b][gid] = a1w[gid];
                S_wsk[0][b][gid] = esw[gid];
                S_wsk[1][b][gid] = asw[gid];
            }
        }
    }
}

// ---------------- K1: forwards k,v,q + (eta,alpha) (grid 128 x 256thr) ----------------
__global__ void __launch_bounds__(256) k1_forward(const float* __restrict__ x, int chunk){
    extern __shared__ float sm[];
    float* Xs  = sm;
    float* Hs  = sm + XTILE;
    float* Bt  = sm + 2*XTILE;
    float* Red = sm + 2*XTILE + BT2;      // 32 floats
    const int tid = threadIdx.x, tx = tid&31;
    const int rw = (tid>>5)&3, jh = tid>>7;
    const int bx = blockIdx.x;
    const int th = bx&3, gg = (bx>>2)&3, b = bx>>4;
    const int tok0 = chunk*CHK + th*16;

    load_tile16(Xs, x + ((size_t)b*TLEN + tok0)*DD);

    u64 acc[4][4];
    if(gg < 3){
        gemmTB(Xs, S_w2[gg][b], Bt, acc);
        __syncthreads();
        #pragma unroll
        for(int r=0;r<4;r++)
            #pragma unroll
            for(int jj=0;jj<4;jj++)
                Hs[(rw*4+r)*SA + jh*128 + tx + 32*jj] = geluf(red2(acc[r][jj]));
        gemmTB(Hs, S_w1f[gg][b], Bt, acc);

        float out[4][4];
        #pragma unroll
        for(int r=0;r<4;r++){
            const int r2 = rw*4+r;
            float s = 0.f;
            #pragma unroll
            for(int jj=0;jj<4;jj++){
                const int col = jh*128 + tx + 32*jj;
                float o = Xs[r2*SA + col] + red2(acc[r][jj]);
                out[r][jj] = o;
                s += (gg==1)? o : o*o;
            }
            s = warp_sum(s);
            if(tx==0) Red[r2*2 + jh] = s;
        }
        __syncthreads();
        if(gg==1){
            #pragma unroll
            for(int r=0;r<4;r++){
                const int r2 = rw*4+r, row = th*16 + r2;
                #pragma unroll
                for(int jj=0;jj<4;jj++)
                    SC_v[b][row*DD + jh*128 + tx + 32*jj] = out[r][jj];
                if(jh==0 && tx==0) SC_vsum[b][row] = Red[r2*2] + Red[r2*2+1];
            }
        } else {
            float* dst = (gg==0)? SC_k[b] : SC_q[b];
            #pragma unroll
            for(int r=0;r<4;r++){
                const int r2 = rw*4+r, row = th*16 + r2;
                float inv = 1.f / fmaxf(sqrtf(Red[r2*2] + Red[r2*2+1]), 1e-6f);
                #pragma unroll
                for(int jj=0;jj<4;jj++)
                    dst[row*DD + jh*128 + tx + 32*jj] = out[r][jj]*inv;
            }
        }
    } else {
        #pragma unroll 1
        for(int si=0;si<2;si++){
            gemmTB(Xs, S_w2[3+si][b], Bt, acc);
            const float* wsk = S_wsk[si][b];
            const float* w1v = S_w1v[si][b];
            #pragma unroll
            for(int r=0;r<4;r++){
                const int r2 = rw*4+r;
                float p = 0.f;
                #pragma unroll
                for(int jj=0;jj<4;jj++){
                    const int col = jh*128 + tx + 32*jj;
                    float h = geluf(red2(acc[r][jj]));
                    p += Xs[r2*SA + col]*wsk[col] + h*w1v[col];
                }
                p = warp_sum(p);
                if(tx==0) Red[r2*2 + jh] = p;
            }
            __syncthreads();
            if(jh==0 && tx==0){
                #pragma unroll
                for(int r=0;r<4;r++){
                    const int r2 = rw*4+r, row = th*16 + r2;
                    float pt = Red[r2*2] + Red[r2*2+1];
                    if(si==0){ float sp = (pt>20.f)? pt : log1pf(expf(pt)); SC_eta[b][row] = sp*0.001f; }
                    else       SC_alpha[b][row] = 1.f/(1.f+expf(-pt));
                }
            }
            __syncthreads();
        }
    }
}

// ---------------- K2: per-token update terms + output (grid 224 x 256thr) ----------------
__global__ void __launch_bounds__(256) k2_token(float* __restrict__ dout, int chunk){
    extern __shared__ float sm[];
    const int tid = threadIdx.x, tx = tid&31;
    const int rw = (tid>>5)&3, jh = tid>>7;
    const int bx = blockIdx.x;
    u64 acc[4][4];

    if(bx < 128){
        float* Ks = sm;
        float* Hs = sm + XTILE;
        float* Gs = sm + 2*XTILE;
        float* Bt = sm + 3*XTILE;
        const int th = bx&3, f = (bx>>2)&3, b = bx>>4;
        const int s = (f==3)? 5 : f;

        load_tile16(Ks, SC_k[b] + th*16*DD);

        float zreg[4][4];
        gemmTB(Ks, S_w2[s][b], Bt, acc);
        __syncthreads();
        #pragma unroll
        for(int r=0;r<4;r++)
            #pragma unroll
            for(int jj=0;jj<4;jj++){
                const int r2 = rw*4+r, col = jh*128 + tx + 32*jj;
                float z = red2(acc[r][jj]); zreg[r][jj] = z;
                float h = geluf(z);
                Hs[r2*SA + col] = h;
                SC_h2[s][b][(th*16 + r2)*DD + col] = h;
            }
        gemmTB(Hs, S_w1f[f][b], Bt, acc);
        __syncthreads();
        #pragma unroll
        for(int r=0;r<4;r++)
            #pragma unroll
            for(int jj=0;jj<4;jj++){
                const int r2 = rw*4+r, col = jh*128 + tx + 32*jj;
                const int row = th*16 + r2;
                float g = 2.f*(Ks[r2*SA + col] + red2(acc[r][jj]) - SC_v[b][row*DD + col]);
                Gs[r2*SA + col] = g;
                SC_g[f][b][row*DD + col] = g;
                Ks[r2*SA + col] = dgeluf(zreg[r][jj]);   // repurpose Ks as dgelu tile
            }
        u64 accN[4][2];
        gemmN(Gs, S_w1f[f][b], Bt, accN);
        #pragma unroll
        for(int r=0;r<4;r++){
            const int r2 = rw*4+r, row = th*16 + r2;
            #pragma unroll
            for(int pp=0;pp<2;pp++){
                float2 v = up2(accN[r][pp]);
                const int c0 = jh*128 + 2*tx + 64*pp;
                SC_pre[s][b][row*DD + c0]     = v.x * Ks[r2*SA + c0];
                SC_pre[s][b][row*DD + c0 + 1] = v.y * Ks[r2*SA + c0 + 1];
            }
        }
    } else if(bx < 192){
        float* Ks  = sm;
        float* Bt  = sm + XTILE;
        float* Red = sm + XTILE + BT2;
        const int i = bx-128, th = i&3, si = (i>>2)&1, b = i>>3;
        const int s = 3+si;

        load_tile16(Ks, SC_k[b] + th*16*DD);

        gemmTB(Ks, S_w2[s][b], Bt, acc);
        const float* wsk = S_wsk[si][b];
        const float* w1v = S_w1v[si][b];
        float zr[4][4];
        #pragma unroll
        for(int r=0;r<4;r++){
            const int r2 = rw*4+r;
            float p = 0.f;
            #pragma unroll
            for(int jj=0;jj<4;jj++){
                const int col = jh*128 + tx + 32*jj;
                float z = red2(acc[r][jj]); zr[r][jj] = z;
                float h = geluf(z);
                SC_h2[s][b][(th*16 + r2)*DD + col] = h;
                p += Ks[r2*SA + col]*wsk[col] + h*w1v[col];
            }
            p = warp_sum(p);
            if(tx==0) Red[r2*2 + jh] = p;
        }
        __syncthreads();
        #pragma unroll
        for(int r=0;r<4;r++){
            const int r2 = rw*4+r, row = th*16 + r2;
            float pt = Red[r2*2] + Red[r2*2+1];
            float g = 2.f*(256.f*pt - SC_vsum[b][row]);
            if(jh==0 && tx==0) SC_gs[si][b][row] = g;
            #pragma unroll
            for(int jj=0;jj<4;jj++){
                const int col = jh*128 + tx + 32*jj;
                SC_pre[s][b][row*DD + col] = g * w1v[col] * dgeluf(zr[r][jj]);
            }
        }
    } else {
        float* Qs = sm;
        float* Hs = sm + XTILE;
        float* Bt = sm + 2*XTILE;
        const int i = bx-192, th = i&3, b = i>>2;

        load_tile16(Qs, SC_q[b] + th*16*DD);

        gemmTB(Qs, S_w2[5][b], Bt, acc);
        __syncthreads();
        #pragma unroll
        for(int r=0;r<4;r++)
            #pragma unroll
            for(int jj=0;jj<4;jj++)
                Hs[(rw*4+r)*SA + jh*128 + tx + 32*jj] = geluf(red2(acc[r][jj]));
        gemmTB(Hs, S_w1f[3][b], Bt, acc);
        #pragma unroll
        for(int r=0;r<4;r++)
            #pragma unroll
            for(int jj=0;jj<4;jj++){
                const int r2 = rw*4+r, col = jh*128 + tx + 32*jj;
                size_t off = ((size_t)b*TLEN + (size_t)chunk*CHK + th*16 + r2)*DD + col;
                dout[off] = Qs[r2*SA + col] + red2(acc[r][jj]);
            }
        if(th==0 && tid==0){
            float p = 1.f;
            #pragma unroll
            for(int t=0;t<CHK;t++) p *= SC_alpha[b][t];
            SC_abar[b] = p;
        }
    }
}

// ---------------- K3: IN-PLACE weight updates (grid 656 x 256thr) ----------------
__global__ void __launch_bounds__(256) k3_weights(){
    extern __shared__ float sm[];
    float* Ges = sm;            // 64 x 66
    float* Bs  = sm + 64*66;    // 64 x 132
    const int tid = threadIdx.x, wid = tid>>5, tx = tid&31;
    const int bx = blockIdx.x;

    if(bx < 640){
        int b, ot, ch;
        const float *A, *Bsrc; float* W;
        if(bx < 512){
            b = bx>>6; int r = bx&63;
            int f = r>>4, m = (r>>3)&1; ot = (r>>1)&3; ch = r&1;
            int s = (f==3)? 5 : f;
            if(m==0){ A = SC_g[f][b];   Bsrc = SC_h2[s][b]; W = S_w1f[f][b]; }
            else    { A = SC_pre[s][b]; Bsrc = SC_k[b];     W = S_w2[s][b];  }
        } else {
            int i = bx-512; b = i>>4; int r = i&15;
            int si = r>>3; ot = (r>>1)&3; ch = r&1;
            int s = 3+si;
            A = SC_pre[s][b]; Bsrc = SC_k[b]; W = S_w2[s][b];
        }
        const float abar = SC_abar[b];
        const float* eta = SC_eta[b];

        #pragma unroll
        for(int l=0;l<8;l++){
            int idx = tid + l*256;
            int t = idx>>5, qc = (idx&31)<<2;
            *reinterpret_cast<float4*>(Bs + t*132 + qc) =
                *reinterpret_cast<const float4*>(Bsrc + t*DD + ch*128 + qc);
        }
        #pragma unroll
        for(int l=0;l<4;l++){
            int idx = tid + l*256;
            int t = idx>>4, oq = (idx&15)<<2;
            float e = eta[t];
            float4 v = *reinterpret_cast<const float4*>(A + t*DD + ot*64 + oq);
            float2* p = reinterpret_cast<float2*>(Ges + t*66 + oq);
            p[0] = make_float2(v.x*e, v.y*e);
            p[1] = make_float2(v.z*e, v.w*e);
        }
        __syncthreads();

        u64 acc[4][4];
        #pragma unroll
        for(int rp=0;rp<4;rp++)
            #pragma unroll
            for(int j=0;j<4;j++) acc[rp][j] = 0ull;

        #pragma unroll 4
        for(int t=0;t<64;t++){
            u64 a[4];
            #pragma unroll
            for(int rp=0;rp<4;rp++)
                a[rp] = *reinterpret_cast<const u64*>(Ges + t*66 + wid*8 + 2*rp);
            float4 bv = *reinterpret_cast<const float4*>(Bs + t*132 + tx*4);
            u64 b0 = pk2(bv.x,bv.x), b1 = pk2(bv.y,bv.y), b2 = pk2(bv.z,bv.z), b3 = pk2(bv.w,bv.w);
            #pragma unroll
            for(int rp=0;rp<4;rp++){
                fmaX2(acc[rp][0], a[rp], b0);
                fmaX2(acc[rp][1], a[rp], b1);
                fmaX2(acc[rp][2], a[rp], b2);
                fmaX2(acc[rp][3], a[rp], b3);
            }
        }
        #pragma unroll
        for(int rp=0;rp<4;rp++){
            const int row0 = ot*64 + wid*8 + 2*rp;
            size_t off0 = (size_t)row0*DD + ch*128 + tx*4;
            float4 w0 = *reinterpret_cast<const float4*>(W + off0);
            float4 w1 = *reinterpret_cast<const float4*>(W + off0 + DD);
            float2 c0 = up2(acc[rp][0]), c1 = up2(acc[rp][1]);
            float2 c2 = up2(acc[rp][2]), c3 = up2(acc[rp][3]);
            float4 o0 = make_float4(abar*w0.x - c0.x, abar*w0.y - c1.x,
                                    abar*w0.z - c2.x, abar*w0.w - c3.x);
            float4 o1 = make_float4(abar*w1.x - c0.y, abar*w1.y - c1.y,
                                    abar*w1.z - c2.y, abar*w1.w - c3.y);
            *reinterpret_cast<float4*>(W + off0)      = o0;
            *reinterpret_cast<float4*>(W + off0 + DD) = o1;
        }
    } else {
        const int i = bx-640, b = i>>1, si = i&1, s = 3+si;
        const float abar = SC_abar[b];
        const int j = tid;
        float aA = 0.f, aB = 0.f;
        #pragma unroll 4
        for(int t=0;t<CHK;t++){
            float ge = SC_gs[si][b][t]*SC_eta[b][t];
            aA += ge * SC_h2[s][b][t*DD + j];
            aB += ge * SC_k[b][t*DD + j];
        }
        S_w1v[si][b][j] = abar*S_w1v[si][b][j] - aA;
        S_wsk[si][b][j] = abar*S_wsk[si][b][j] - aB;
    }
}

// ---------------- launch ----------------
#define SMEM1 ((2*XTILE + BT2 + 32)*4)       // 103168 B
#define SMEM2 ((3*XTILE + BT2 + 32)*4)       // 119808 B
#define SMEM3 ((64*66 + 64*132)*4)           //  50688 B

extern "C" void kernel_launch(void* const* d_in, const int* in_sizes, int n_in,
                              void* d_out, int out_size){
    (void)in_sizes; (void)n_in; (void)out_size;
    const float* x   = (const float*)d_in[0];
    const float* k1w = (const float*)d_in[1];
    const float* k2w = (const float*)d_in[2];
    const float* v1w = (const float*)d_in[3];
    const float* v2w = (const float*)d_in[4];
    const float* q1w = (const float*)d_in[5];
    const float* q2w = (const float*)d_in[6];
    const float* e1w = (const float*)d_in[7];
    const float* e2w = (const float*)d_in[8];
    const float* esw = (const float*)d_in[9];
    const float* a1w = (const float*)d_in[10];
    const float* a2w = (const float*)d_in[11];
    const float* asw = (const float*)d_in[12];
    const float* m1w = (const float*)d_in[13];
    const float* m2w = (const float*)d_in[14];
    float* out = (float*)d_out;

    cudaFuncSetAttribute(k1_forward, cudaFuncAttributeMaxDynamicSharedMemorySize, SMEM1);
    cudaFuncSetAttribute(k2_token,   cudaFuncAttributeMaxDynamicSharedMemorySize, SMEM2);
    cudaFuncSetAttribute(k3_weights, cudaFuncAttributeMaxDynamicSharedMemorySize, SMEM3);

    k0_init<<<dim3(DD*DD/256, 11), 256>>>(k1w,k2w,v1w,v2w,q1w,q2w,e1w,e2w,esw,a1w,a2w,asw,m1w,m2w);

    for(int c=0;c<NC;c++){
        k1_forward<<<128, 256, SMEM1>>>(x, c);
        k2_token  <<<224, 256, SMEM2>>>(out, c);
        k3_weights<<<656, 256, SMEM3>>>();
    }
}

// round 9
// speedup vs baseline: 1.0880x; 1.0022x over previous
#include <cuda_runtime.h>
#include <math.h>

typedef unsigned long long u64;

#define DD   256
#define BB   8
#define CHK  64
#define NC   64
#define TLEN 4096

#define SA    260               // activation tile row stride (floats)
#define STB   34                // B^T staging stride (conflict-free LDS.64)
#define SNB   260               // normal-orientation staging stride
#define XTILE (16*SA)           // 4160 floats
#define BT2   17408             // double buffer: max(2*256*34, 2*32*260) floats

// ---------------- persistent state (IN-PLACE updated, single buffer) ----------------
// states: 0=k 1=v 2=q 3=eta 4=alpha 5=mem ; full-w1 index f: k,v,q,mem -> 0,1,2,3
static __device__ float S_w1f[4][BB][DD*DD];
static __device__ float S_w2 [6][BB][DD*DD];
static __device__ float S_w1v[2][BB][DD];
static __device__ float S_wsk[2][BB][DD];

// ---------------- per-chunk scratch ----------------
static __device__ float SC_k [BB][CHK*DD];
static __device__ float SC_v [BB][CHK*DD];
static __device__ float SC_q [BB][CHK*DD];
static __device__ float SC_h2[6][BB][CHK*DD];
static __device__ float SC_g [4][BB][CHK*DD];
static __device__ float SC_pre[6][BB][CHK*DD];
static __device__ float SC_eta[BB][CHK];
static __device__ float SC_alpha[BB][CHK];
static __device__ float SC_vsum[BB][CHK];
static __device__ float SC_gs[2][BB][CHK];
static __device__ float SC_abar[BB];

// ---------------- helpers ----------------
__device__ __forceinline__ void fmaX2(u64 &d, u64 a, u64 b){
    asm("fma.rn.f32x2 %0, %1, %2, %0;" : "+l"(d) : "l"(a), "l"(b));
}
__device__ __forceinline__ u64 pk2(float lo, float hi){
    u64 r; asm("mov.b64 %0, {%1, %2};" : "=l"(r) : "f"(lo), "f"(hi)); return r;
}
__device__ __forceinline__ float2 up2(u64 v){
    float lo, hi; asm("mov.b64 {%0, %1}, %2;" : "=f"(lo), "=f"(hi) : "l"(v));
    return make_float2(lo, hi);
}
__device__ __forceinline__ float red2(u64 v){ float2 t = up2(v); return t.x + t.y; }

__device__ __forceinline__ float geluf(float z){
    return 0.5f*z*(1.0f + erff(z*0.70710678118654752f));
}
__device__ __forceinline__ float dgeluf(float z){
    float cdf = 0.5f*(1.0f + erff(z*0.70710678118654752f));
    float pdf = expf(-0.5f*z*z)*0.39894228040143267f;
    return cdf + z*pdf;
}
__device__ __forceinline__ float warp_sum(float v){
    #pragma unroll
    for(int o=16;o>0;o>>=1) v += __shfl_xor_sync(0xffffffffu, v, o);
    return v;
}

// load 16x256 global -> smem tile (stride SA), 256 threads
__device__ __forceinline__ void load_tile16(float* dst, const float* __restrict__ src){
    const int tid = threadIdx.x;
    #pragma unroll
    for(int l=0;l<4;l++){
        int idx = tid + l*256;            // 1024 float4s
        int r = idx>>6, qc = (idx&63)<<2;
        *reinterpret_cast<float4*>(dst + r*SA + qc) =
            *reinterpret_cast<const float4*>(src + r*DD + qc);
    }
}

// ---------------- TB GEMM (256 thr, reg-staged double-buffered panels) --------------
// OUT[t,col] = sum_c A[t,c]*B[col,c]; warps: rw=(wid&3) rows rw*4..+3 ;
// jh=wid>>2 cols jh*128 + tx + 32*jj (jj<4). Panels of 32 k.
__device__ __forceinline__ void gemmTB(const float* As, const float* __restrict__ Bg,
                                       float* Bt, u64 (&acc)[4][4]){
    const int tid = threadIdx.x, tx = tid&31;
    const int rw = (tid>>5)&3, jh = tid>>7;
    const int j0 = tid>>3, qc = (tid&7)<<2;     // staged rows j0+32l, cols qc..qc+3
    #pragma unroll
    for(int r=0;r<4;r++)
        #pragma unroll
        for(int j=0;j<4;j++) acc[r][j] = 0ull;

    float4 rb[8];
    #pragma unroll
    for(int l=0;l<8;l++)
        rb[l] = *reinterpret_cast<const float4*>(Bg + (size_t)(j0+32*l)*DD + qc);
    #pragma unroll
    for(int l=0;l<8;l++){
        float2* p = reinterpret_cast<float2*>(Bt + (j0+32*l)*STB + qc);
        p[0] = make_float2(rb[l].x, rb[l].y);
        p[1] = make_float2(rb[l].z, rb[l].w);
    }
    __syncthreads();

    #pragma unroll 2
    for(int p=0;p<8;p++){
        if(p<7){
            const float* src = Bg + (p+1)*32 + qc;
            #pragma unroll
            for(int l=0;l<8;l++)
                rb[l] = *reinterpret_cast<const float4*>(src + (size_t)(j0+32*l)*DD);
        }
        const float* Ar = As + rw*4*SA + p*32;
        const float* Bl = Bt + (p&1)*256*STB + (jh*128 + tx)*STB;
        #pragma unroll
        for(int c2=0;c2<16;c2++){
            u64 a0 = *reinterpret_cast<const u64*>(Ar + 0*SA + 2*c2);
            u64 a1 = *reinterpret_cast<const u64*>(Ar + 1*SA + 2*c2);
            u64 a2 = *reinterpret_cast<const u64*>(Ar + 2*SA + 2*c2);
            u64 a3 = *reinterpret_cast<const u64*>(Ar + 3*SA + 2*c2);
            #pragma unroll
            for(int jj=0;jj<4;jj++){
                u64 b = *reinterpret_cast<const u64*>(Bl + jj*32*STB + 2*c2);
                fmaX2(acc[0][jj], a0, b);
                fmaX2(acc[1][jj], a1, b);
                fmaX2(acc[2][jj], a2, b);
                fmaX2(acc[3][jj], a3, b);
            }
        }
        if(p<7){
            float* dstb = Bt + ((p+1)&1)*256*STB;
            #pragma unroll
            for(int l=0;l<8;l++){
                float2* q = reinterpret_cast<float2*>(dstb + (j0+32*l)*STB + qc);
                q[0] = make_float2(rb[l].x, rb[l].y);
                q[1] = make_float2(rb[l].z, rb[l].w);
            }
            __syncthreads();
        }
    }
}

// ---------------- normal GEMM (256 thr, reg-staged double-buffered panels) ----------
// OUT[t,j]=sum_c A[t,c]*B[c,j]; cols jh*128 + 2*tx + 64*pp (+1), pp<2.
__device__ __forceinline__ void gemmN(const float* As, const float* __restrict__ Bg,
                                      float* Bt, u64 (&acc)[4][2]){
    const int tid = threadIdx.x, tx = tid&31;
    const int rw = (tid>>5)&3, jh = tid>>7;
    const int cc0 = tid>>6, qn = (tid&63)<<2;   // staged rows cc0+4l, cols qn..qn+3
    #pragma unroll
    for(int r=0;r<4;r++)
        #pragma unroll
        for(int pp=0;pp<2;pp++) acc[r][pp] = 0ull;

    float4 rb[8];
    #pragma unroll
    for(int l=0;l<8;l++)
        rb[l] = *reinterpret_cast<const float4*>(Bg + (size_t)(cc0+4*l)*DD + qn);
    #pragma unroll
    for(int l=0;l<8;l++)
        *reinterpret_cast<float4*>(Bt + (cc0+4*l)*SNB + qn) = rb[l];
    __syncthreads();

    #pragma unroll 2
    for(int p=0;p<8;p++){
        if(p<7){
            const float* src = Bg + (size_t)((p+1)*32 + cc0)*DD + qn;
            #pragma unroll
            for(int l=0;l<8;l++)
                rb[l] = *reinterpret_cast<const float4*>(src + (size_t)(4*l)*DD);
        }
        const float* Ar = As + rw*4*SA + p*32;
        const float* Bl = Bt + (p&1)*32*SNB + jh*128 + 2*tx;
        #pragma unroll
        for(int cc=0;cc<32;cc++){
            u64 a0 = pk2(Ar[0*SA+cc], Ar[0*SA+cc]);
            u64 a1 = pk2(Ar[1*SA+cc], Ar[1*SA+cc]);
            u64 a2 = pk2(Ar[2*SA+cc], Ar[2*SA+cc]);
            u64 a3 = pk2(Ar[3*SA+cc], Ar[3*SA+cc]);
            #pragma unroll
            for(int pp=0;pp<2;pp++){
                u64 b = *reinterpret_cast<const u64*>(Bl + cc*SNB + 64*pp);
                fmaX2(acc[0][pp], a0, b);
                fmaX2(acc[1][pp], a1, b);
                fmaX2(acc[2][pp], a2, b);
                fmaX2(acc[3][pp], a3, b);
            }
        }
        if(p<7){
            float* dstb = Bt + ((p+1)&1)*32*SNB;
            #pragma unroll
            for(int l=0;l<8;l++)
                *reinterpret_cast<float4*>(dstb + (cc0+4*l)*SNB + qn) = rb[l];
            __syncthreads();
        }
    }
}

// ---------------- K0: initialize per-batch state ----------------
__global__ void k0_init(const float* __restrict__ k1w, const float* __restrict__ k2w,
                        const float* __restrict__ v1w, const float* __restrict__ v2w,
                        const float* __restrict__ q1w, const float* __restrict__ q2w,
                        const float* __restrict__ e1w, const float* __restrict__ e2w,
                        const float* __restrict__ esw, const float* __restrict__ a1w,
                        const float* __restrict__ a2w, const float* __restrict__ asw,
                        const float* __restrict__ m1w, const float* __restrict__ m2w){
    const int gid = blockIdx.x*blockDim.x + threadIdx.x;
    const int m = blockIdx.y;
    if(m<4){
        const float* src = (m==0)?k1w:(m==1)?v1w:(m==2)?q1w:m1w;
        float v = src[gid];
        #pragma unroll
        for(int b=0;b<BB;b++) S_w1f[m][b][gid] = v;
    } else if(m<10){
        const int s = m-4;
        const float* src = (s==0)?k2w:(s==1)?v2w:(s==2)?q2w:(s==3)?e2w:(s==4)?a2w:m2w;
        float v = src[gid];
        #pragma unroll
        for(int b=0;b<BB;b++) S_w2[s][b][gid] = v;
    } else {
        if(gid < DD){
            #pragma unroll
            for(int b=0;b<BB;b++){
                S_w1v[0][b][gid] = e1w[gid];
                S_w1v[1][b][gid] = a1w[gid];
                S_wsk[0][b][gid] = esw[gid];
                S_wsk[1][b][gid] = asw[gid];
            }
        }
    }
}

// ---------------- K1: forwards k,v,q + (eta,alpha) (grid 128 x 256thr) ----------------
__global__ void __launch_bounds__(256) k1_forward(const float* __restrict__ x, int chunk){
    extern __shared__ float sm[];
    float* Xs  = sm;
    float* Hs  = sm + XTILE;
    float* Bt  = sm + 2*XTILE;
    float* Red = sm + 2*XTILE + BT2;      // 32 floats
    const int tid = threadIdx.x, tx = tid&31;
    const int rw = (tid>>5)&3, jh = tid>>7;
    const int bx = blockIdx.x;
    const int th = bx&3, gg = (bx>>2)&3, b = bx>>4;
    const int tok0 = chunk*CHK + th*16;

    load_tile16(Xs, x + ((size_t)b*TLEN + tok0)*DD);

    u64 acc[4][4];
    if(gg < 3){
        gemmTB(Xs, S_w2[gg][b], Bt, acc);
        __syncthreads();
        #pragma unroll
        for(int r=0;r<4;r++)
            #pragma unroll
            for(int jj=0;jj<4;jj++)
                Hs[(rw*4+r)*SA + jh*128 + tx + 32*jj] = geluf(red2(acc[r][jj]));
        gemmTB(Hs, S_w1f[gg][b], Bt, acc);

        float out[4][4];
        #pragma unroll
        for(int r=0;r<4;r++){
            const int r2 = rw*4+r;
            float s = 0.f;
            #pragma unroll
            for(int jj=0;jj<4;jj++){
                const int col = jh*128 + tx + 32*jj;
                float o = Xs[r2*SA + col] + red2(acc[r][jj]);
                out[r][jj] = o;
                s += (gg==1)? o : o*o;
            }
            s = warp_sum(s);
            if(tx==0) Red[r2*2 + jh] = s;
        }
        __syncthreads();
        if(gg==1){
            #pragma unroll
            for(int r=0;r<4;r++){
                const int r2 = rw*4+r, row = th*16 + r2;
                #pragma unroll
                for(int jj=0;jj<4;jj++)
                    SC_v[b][row*DD + jh*128 + tx + 32*jj] = out[r][jj];
                if(jh==0 && tx==0) SC_vsum[b][row] = Red[r2*2] + Red[r2*2+1];
            }
        } else {
            float* dst = (gg==0)? SC_k[b] : SC_q[b];
            #pragma unroll
            for(int r=0;r<4;r++){
                const int r2 = rw*4+r, row = th*16 + r2;
                float inv = 1.f / fmaxf(sqrtf(Red[r2*2] + Red[r2*2+1]), 1e-6f);
                #pragma unroll
                for(int jj=0;jj<4;jj++)
                    dst[row*DD + jh*128 + tx + 32*jj] = out[r][jj]*inv;
            }
        }
    } else {
        #pragma unroll 1
        for(int si=0;si<2;si++){
            gemmTB(Xs, S_w2[3+si][b], Bt, acc);
            const float* wsk = S_wsk[si][b];
            const float* w1v = S_w1v[si][b];
            #pragma unroll
            for(int r=0;r<4;r++){
                const int r2 = rw*4+r;
                float p = 0.f;
                #pragma unroll
                for(int jj=0;jj<4;jj++){
                    const int col = jh*128 + tx + 32*jj;
                    float h = geluf(red2(acc[r][jj]));
                    p += Xs[r2*SA + col]*wsk[col] + h*w1v[col];
                }
                p = warp_sum(p);
                if(tx==0) Red[r2*2 + jh] = p;
            }
            __syncthreads();
            if(jh==0 && tx==0){
                #pragma unroll
                for(int r=0;r<4;r++){
                    const int r2 = rw*4+r, row = th*16 + r2;
                    float pt = Red[r2*2] + Red[r2*2+1];
                    if(si==0){ float sp = (pt>20.f)? pt : log1pf(expf(pt)); SC_eta[b][row] = sp*0.001f; }
                    else       SC_alpha[b][row] = 1.f/(1.f+expf(-pt));
                }
            }
            __syncthreads();
        }
    }
}

// ---------------- K2: per-token update terms + output (grid 224 x 256thr) ----------------
__global__ void __launch_bounds__(256) k2_token(float* __restrict__ dout, int chunk){
    extern __shared__ float sm[];
    const int tid = threadIdx.x, tx = tid&31;
    const int rw = (tid>>5)&3, jh = tid>>7;
    const int bx = blockIdx.x;
    u64 acc[4][4];

    if(bx < 128){
        float* Ks = sm;
        float* Hs = sm + XTILE;
        float* Gs = sm + 2*XTILE;
        float* Bt = sm + 3*XTILE;
        const int th = bx&3, f = (bx>>2)&3, b = bx>>4;
        const int s = (f==3)? 5 : f;

        load_tile16(Ks, SC_k[b] + th*16*DD);

        float zreg[4][4];
        gemmTB(Ks, S_w2[s][b], Bt, acc);
        __syncthreads();
        #pragma unroll
        for(int r=0;r<4;r++)
            #pragma unroll
            for(int jj=0;jj<4;jj++){
                const int r2 = rw*4+r, col = jh*128 + tx + 32*jj;
                float z = red2(acc[r][jj]); zreg[r][jj] = z;
                float h = geluf(z);
                Hs[r2*SA + col] = h;
                SC_h2[s][b][(th*16 + r2)*DD + col] = h;
            }
        gemmTB(Hs, S_w1f[f][b], Bt, acc);
        __syncthreads();
        #pragma unroll
        for(int r=0;r<4;r++)
            #pragma unroll
            for(int jj=0;jj<4;jj++){
                const int r2 = rw*4+r, col = jh*128 + tx + 32*jj;
                const int row = th*16 + r2;
                float g = 2.f*(Ks[r2*SA + col] + red2(acc[r][jj]) - SC_v[b][row*DD + col]);
                Gs[r2*SA + col] = g;
                SC_g[f][b][row*DD + col] = g;
                Ks[r2*SA + col] = dgeluf(zreg[r][jj]);   // repurpose Ks as dgelu tile
            }
        u64 accN[4][2];
        gemmN(Gs, S_w1f[f][b], Bt, accN);
        #pragma unroll
        for(int r=0;r<4;r++){
            const int r2 = rw*4+r, row = th*16 + r2;
            #pragma unroll
            for(int pp=0;pp<2;pp++){
                float2 v = up2(accN[r][pp]);
                const int c0 = jh*128 + 2*tx + 64*pp;
                SC_pre[s][b][row*DD + c0]     = v.x * Ks[r2*SA + c0];
                SC_pre[s][b][row*DD + c0 + 1] = v.y * Ks[r2*SA + c0 + 1];
            }
        }
    } else if(bx < 192){
        float* Ks  = sm;
        float* Bt  = sm + XTILE;
        float* Red = sm + XTILE + BT2;
        const int i = bx-128, th = i&3, si = (i>>2)&1, b = i>>3;
        const int s = 3+si;

        load_tile16(Ks, SC_k[b] + th*16*DD);

        gemmTB(Ks, S_w2[s][b], Bt, acc);
        const float* wsk = S_wsk[si][b];
        const float* w1v = S_w1v[si][b];
        float zr[4][4];
        #pragma unroll
        for(int r=0;r<4;r++){
            const int r2 = rw*4+r;
            float p = 0.f;
            #pragma unroll
            for(int jj=0;jj<4;jj++){
                const int col = jh*128 + tx + 32*jj;
                float z = red2(acc[r][jj]); zr[r][jj] = z;
                float h = geluf(z);
                SC_h2[s][b][(th*16 + r2)*DD + col] = h;
                p += Ks[r2*SA + col]*wsk[col] + h*w1v[col];
            }
            p = warp_sum(p);
            if(tx==0) Red[r2*2 + jh] = p;
        }
        __syncthreads();
        #pragma unroll
        for(int r=0;r<4;r++){
            const int r2 = rw*4+r, row = th*16 + r2;
            float pt = Red[r2*2] + Red[r2*2+1];
            float g = 2.f*(256.f*pt - SC_vsum[b][row]);
            if(jh==0 && tx==0) SC_gs[si][b][row] = g;
            #pragma unroll
            for(int jj=0;jj<4;jj++){
                const int col = jh*128 + tx + 32*jj;
                SC_pre[s][b][row*DD + col] = g * w1v[col] * dgeluf(zr[r][jj]);
            }
        }
    } else {
        float* Qs = sm;
        float* Hs = sm + XTILE;
        float* Bt = sm + 2*XTILE;
        const int i = bx-192, th = i&3, b = i>>2;

        load_tile16(Qs, SC_q[b] + th*16*DD);

        gemmTB(Qs, S_w2[5][b], Bt, acc);
        __syncthreads();
        #pragma unroll
        for(int r=0;r<4;r++)
            #pragma unroll
            for(int jj=0;jj<4;jj++)
                Hs[(rw*4+r)*SA + jh*128 + tx + 32*jj] = geluf(red2(acc[r][jj]));
        gemmTB(Hs, S_w1f[3][b], Bt, acc);
        #pragma unroll
        for(int r=0;r<4;r++)
            #pragma unroll
            for(int jj=0;jj<4;jj++){
                const int r2 = rw*4+r, col = jh*128 + tx + 32*jj;
                size_t off = ((size_t)b*TLEN + (size_t)chunk*CHK + th*16 + r2)*DD + col;
                dout[off] = Qs[r2*SA + col] + red2(acc[r][jj]);
            }
        if(th==0 && tid==0){
            float p = 1.f;
            #pragma unroll
            for(int t=0;t<CHK;t++) p *= SC_alpha[b][t];
            SC_abar[b] = p;
        }
    }
}

// ---------------- K3: IN-PLACE weight updates (grid 656 x 256thr) ----------------
__global__ void __launch_bounds__(256) k3_weights(){
    extern __shared__ float sm[];
    float* Ges = sm;            // 64 x 66
    float* Bs  = sm + 64*66;    // 64 x 132
    const int tid = threadIdx.x, wid = tid>>5, tx = tid&31;
    const int bx = blockIdx.x;

    if(bx < 640){
        int b, ot, ch;
        const float *A, *Bsrc; float* W;
        if(bx < 512){
            b = bx>>6; int r = bx&63;
            int f = r>>4, m = (r>>3)&1; ot = (r>>1)&3; ch = r&1;
            int s = (f==3)? 5 : f;
            if(m==0){ A = SC_g[f][b];   Bsrc = SC_h2[s][b]; W = S_w1f[f][b]; }
            else    { A = SC_pre[s][b]; Bsrc = SC_k[b];     W = S_w2[s][b];  }
        } else {
            int i = bx-512; b = i>>4; int r = i&15;
            int si = r>>3; ot = (r>>1)&3; ch = r&1;
            int s = 3+si;
            A = SC_pre[s][b]; Bsrc = SC_k[b]; W = S_w2[s][b];
        }
        const float abar = SC_abar[b];
        const float* eta = SC_eta[b];

        #pragma unroll
        for(int l=0;l<8;l++){
            int idx = tid + l*256;
            int t = idx>>5, qc = (idx&31)<<2;
            *reinterpret_cast<float4*>(Bs + t*132 + qc) =
                *reinterpret_cast<const float4*>(Bsrc + t*DD + ch*128 + qc);
        }
        #pragma unroll
        for(int l=0;l<4;l++){
            int idx = tid + l*256;
            int t = idx>>4, oq = (idx&15)<<2;
            float e = eta[t];
            float4 v = *reinterpret_cast<const float4*>(A + t*DD + ot*64 + oq);
            float2* p = reinterpret_cast<float2*>(Ges + t*66 + oq);
            p[0] = make_float2(v.x*e, v.y*e);
            p[1] = make_float2(v.z*e, v.w*e);
        }
        __syncthreads();

        u64 acc[4][4];
        #pragma unroll
        for(int rp=0;rp<4;rp++)
            #pragma unroll
            for(int j=0;j<4;j++) acc[rp][j] = 0ull;

        #pragma unroll 4
        for(int t=0;t<64;t++){
            u64 a[4];
            #pragma unroll
            for(int rp=0;rp<4;rp++)
                a[rp] = *reinterpret_cast<const u64*>(Ges + t*66 + wid*8 + 2*rp);
            float4 bv = *reinterpret_cast<const float4*>(Bs + t*132 + tx*4);
            u64 b0 = pk2(bv.x,bv.x), b1 = pk2(bv.y,bv.y), b2 = pk2(bv.z,bv.z), b3 = pk2(bv.w,bv.w);
            #pragma unroll
            for(int rp=0;rp<4;rp++){
                fmaX2(acc[rp][0], a[rp], b0);
                fmaX2(acc[rp][1], a[rp], b1);
                fmaX2(acc[rp][2], a[rp], b2);
                fmaX2(acc[rp][3], a[rp], b3);
            }
        }
        #pragma unroll
        for(int rp=0;rp<4;rp++){
            const int row0 = ot*64 + wid*8 + 2*rp;
            size_t off0 = (size_t)row0*DD + ch*128 + tx*4;
            float4 w0 = *reinterpret_cast<const float4*>(W + off0);
            float4 w1 = *reinterpret_cast<const float4*>(W + off0 + DD);
            float2 c0 = up2(acc[rp][0]), c1 = up2(acc[rp][1]);
            float2 c2 = up2(acc[rp][2]), c3 = up2(acc[rp][3]);
            float4 o0 = make_float4(abar*w0.x - c0.x, abar*w0.y - c1.x,
                                    abar*w0.z - c2.x, abar*w0.w - c3.x);
            float4 o1 = make_float4(abar*w1.x - c0.y, abar*w1.y - c1.y,
                                    abar*w1.z - c2.y, abar*w1.w - c3.y);
            *reinterpret_cast<float4*>(W + off0)      = o0;
            *reinterpret_cast<float4*>(W + off0 + DD) = o1;
        }
    } else {
        const int i = bx-640, b = i>>1, si = i&1, s = 3+si;
        const float abar = SC_abar[b];
        const int j = tid;
        float aA = 0.f, aB = 0.f;
        #pragma unroll 4
        for(int t=0;t<CHK;t++){
            float ge = SC_gs[si][b][t]*SC_eta[b][t];
            aA += ge * SC_h2[s][b][t*DD + j];
            aB += ge * SC_k[b][t*DD + j];
        }
        S_w1v[si][b][j] = abar*S_w1v[si][b][j] - aA;
        S_wsk[si][b][j] = abar*S_wsk[si][b][j] - aB;
    }
}

// ---------------- launch ----------------
#define SMEM1 ((2*XTILE + BT2 + 32)*4)       // 103168 B
#define SMEM2 ((3*XTILE + BT2 + 32)*4)       // 119808 B
#define SMEM3 ((64*66 + 64*132)*4)           //  50688 B

extern "C" void kernel_launch(void* const* d_in, const int* in_sizes, int n_in,
                              void* d_out, int out_size){
    (void)in_sizes; (void)n_in; (void)out_size;
    const float* x   = (const float*)d_in[0];
    const float* k1w = (const float*)d_in[1];
    const float* k2w = (const float*)d_in[2];
    const float* v1w = (const float*)d_in[3];
    const float* v2w = (const float*)d_in[4];
    const float* q1w = (const float*)d_in[5];
    const float* q2w = (const float*)d_in[6];
    const float* e1w = (const float*)d_in[7];
    const float* e2w = (const float*)d_in[8];
    const float* esw = (const float*)d_in[9];
    const float* a1w = (const float*)d_in[10];
    const float* a2w = (const float*)d_in[11];
    const float* asw = (const float*)d_in[12];
    const float* m1w = (const float*)d_in[13];
    const float* m2w = (const float*)d_in[14];
    float* out = (float*)d_out;

    cudaFuncSetAttribute(k1_forward, cudaFuncAttributeMaxDynamicSharedMemorySize, SMEM1);
    cudaFuncSetAttribute(k2_token,   cudaFuncAttributeMaxDynamicSharedMemorySize, SMEM2);
    cudaFuncSetAttribute(k3_weights, cudaFuncAttributeMaxDynamicSharedMemorySize, SMEM3);

    k0_init<<<dim3(DD*DD/256, 11), 256>>>(k1w,k2w,v1w,v2w,q1w,q2w,e1w,e2w,esw,a1w,a2w,asw,m1w,m2w);

    for(int c=0;c<NC;c++){
        k1_forward<<<128, 256, SMEM1>>>(x, c);
        k2_token  <<<224, 256, SMEM2>>>(out, c);
        k3_weights<<<656, 256, SMEM3>>>();
    }
}